// round 12
// baseline (speedup 1.0000x reference)
#include <cuda_runtime.h>
#include <cuda_bf16.h>
#include <math.h>
#include <float.h>
#include <stdint.h>

#define Dd   2048
#define Hh   16
#define HD   128
#define HALF 64
#define FFd  8192
#define Bb   4
#define Ss   2048
#define KK   1024
#define MTOT (Bb * KK)
#define BH   (Bb * Hh)
#define EPSf 1e-6f
#define SM_SCALE 0.08838834764831843f

typedef __nv_bfloat16 bf16;

// ----------------------------------------------------------------------------
// Scratch (device globals)
// ----------------------------------------------------------------------------
__device__ float g_weights[Bb * Ss];
__device__ int   g_kidx[MTOT];
__device__ int   g_kpos[MTOT];
__device__ float g_X  [(size_t)MTOT * Dd];
__device__ float g_h1 [(size_t)MTOT * Dd];
__device__ float g_q  [(size_t)MTOT * Dd];
__device__ float g_k  [(size_t)MTOT * Dd];
__device__ float g_v  [(size_t)MTOT * Dd];
__device__ float g_scores[(size_t)BH * KK * KK];
__device__ float g_att[(size_t)MTOT * Dd];
__device__ float g_ao [(size_t)MTOT * Dd];
__device__ float g_h2n[(size_t)MTOT * Dd];
__device__ float g_ffh[(size_t)MTOT * FFd];
__device__ float g_delta[(size_t)MTOT * Dd];

// pre-split bf16 B operands [N][K]
__device__ bf16 g_WqkvThi[(size_t)3 * Dd * Dd], g_WqkvTlo[(size_t)3 * Dd * Dd];
__device__ bf16 g_WoThi[(size_t)Dd * Dd],  g_WoTlo[(size_t)Dd * Dd];
__device__ bf16 g_W1Thi[(size_t)FFd * Dd], g_W1Tlo[(size_t)FFd * Dd];
__device__ bf16 g_W2Thi[(size_t)Dd * FFd], g_W2Tlo[(size_t)Dd * FFd];
__device__ bf16 g_vThi[(size_t)BH * HD * KK], g_vTlo[(size_t)BH * HD * KK];

// ----------------------------------------------------------------------------
// Helpers
// ----------------------------------------------------------------------------
__device__ __forceinline__ float warpReduceSum(float v) {
#pragma unroll
    for (int o = 16; o > 0; o >>= 1) v += __shfl_xor_sync(0xffffffffu, v, o);
    return v;
}
__device__ __forceinline__ float warpReduceMax(float v) {
#pragma unroll
    for (int o = 16; o > 0; o >>= 1) v = fmaxf(v, __shfl_xor_sync(0xffffffffu, v, o));
    return v;
}
__device__ float blockReduceSum(float v) {
    __shared__ float sm[8];
    __shared__ float res;
    int lane = threadIdx.x & 31, w = threadIdx.x >> 5;
    int nw = (blockDim.x + 31) >> 5;
    v = warpReduceSum(v);
    if (lane == 0) sm[w] = v;
    __syncthreads();
    if (w == 0) {
        float x = (lane < nw) ? sm[lane] : 0.f;
        x = warpReduceSum(x);
        if (lane == 0) res = x;
    }
    __syncthreads();
    return res;
}
__device__ float blockReduceMax(float v) {
    __shared__ float sm[8];
    __shared__ float res;
    int lane = threadIdx.x & 31, w = threadIdx.x >> 5;
    int nw = (blockDim.x + 31) >> 5;
    v = warpReduceMax(v);
    if (lane == 0) sm[w] = v;
    __syncthreads();
    if (w == 0) {
        float x = (lane < nw) ? sm[lane] : -FLT_MAX;
        x = warpReduceMax(x);
        if (lane == 0) res = x;
    }
    __syncthreads();
    return res;
}
__device__ __forceinline__ float gelu_tanh(float x) {
    float x3 = x * x * x;
    float t = tanhf(0.7978845608028654f * (x + 0.044715f * x3));
    return 0.5f * x * (1.f + t);
}
__device__ __forceinline__ uint32_t smem_u32(const void* p) {
    uint32_t a;
    asm("{ .reg .u64 t; cvta.to.shared.u64 t, %1; cvt.u32.u64 %0, t; }" : "=r"(a) : "l"(p));
    return a;
}
__device__ __forceinline__ void cvt_hilo(float a, float b, uint32_t& h, uint32_t& l) {
    __nv_bfloat162 hv = __floats2bfloat162_rn(a, b);
    h = *reinterpret_cast<uint32_t*>(&hv);
    float fa = __uint_as_float(h << 16);
    float fb = __uint_as_float(h & 0xffff0000u);
    __nv_bfloat162 lv = __floats2bfloat162_rn(a - fa, b - fb);
    l = *reinterpret_cast<uint32_t*>(&lv);
}
__device__ __forceinline__ void store_hilo(bf16* H, bf16* L, size_t i, float v) {
    bf16 h = __float2bfloat16(v);
    H[i] = h;
    L[i] = __float2bfloat16(v - __bfloat162float(h));
}

// ----------------------------------------------------------------------------
// HMMA primitives
// ----------------------------------------------------------------------------
__device__ __forceinline__ void ldsm4(uint32_t* r, uint32_t a) {
    asm volatile("ldmatrix.sync.aligned.m8n8.x4.shared.b16 {%0,%1,%2,%3}, [%4];"
        : "=r"(r[0]), "=r"(r[1]), "=r"(r[2]), "=r"(r[3]) : "r"(a));
}
__device__ __forceinline__ void ldsm2(uint32_t* r, uint32_t a) {
    asm volatile("ldmatrix.sync.aligned.m8n8.x2.shared.b16 {%0,%1}, [%2];"
        : "=r"(r[0]), "=r"(r[1]) : "r"(a));
}
__device__ __forceinline__ void mma16816(float* c, const uint32_t* a, const uint32_t* b) {
    asm volatile("mma.sync.aligned.m16n8k16.row.col.f32.bf16.bf16.f32 "
        "{%0,%1,%2,%3}, {%4,%5,%6,%7}, {%8,%9}, {%0,%1,%2,%3};"
        : "+f"(c[0]), "+f"(c[1]), "+f"(c[2]), "+f"(c[3])
        : "r"(a[0]), "r"(a[1]), "r"(a[2]), "r"(a[3]), "r"(b[0]), "r"(b[1]));
}

// SMEM layout per stage: Ahi, Alo, Bhi, Blo tiles of 128 rows x 32 bf16, 80B rows
#define ROWB    80
#define TILE_B  10240
#define STAGE_B 40960
#define HG_SMEM (2 * STAGE_B)

// ----------------------------------------------------------------------------
// Split-bf16 HMMA GEMM body (R6 schedule: register prefetch + double buffer).
// A fp32 (inline hi/lo convert); B either fp32 (BSPLIT=0) or pre-split bf16.
// mode: 0 = C; 1 = C += Add; 2 = gelu(C)
// ----------------------------------------------------------------------------
template<int BSPLIT>
__device__ __forceinline__ void hg_body(
    const float* __restrict__ Af, int lda,
    const float* __restrict__ Bf,
    const bf16* __restrict__ Bhi, const bf16* __restrict__ Blo, int ldb,
    float* __restrict__ C, const float* __restrict__ Add, int ldc,
    int Kd, int m0, int n0, int n0c, int mode)
{
    extern __shared__ char smc[];
    const uint32_t sbase = smem_u32(smc);
    const int tid  = threadIdx.x;
    const int wid  = tid >> 5, lane = tid & 31;
    const int wm   = (wid >> 2) * 64;
    const int wn   = (wid & 3) * 32;
    const int lrow = tid >> 1;
    const int seg  = tid & 1;

    const float4* gA  = (const float4*)(Af + (size_t)(m0 + lrow) * lda);
    const float4* gBf = nullptr;
    const uint4 *gBh = nullptr, *gBl = nullptr;
    if (BSPLIT) {
        gBh = (const uint4*)(Bhi + (size_t)(n0 + lrow) * ldb);
        gBl = (const uint4*)(Blo + (size_t)(n0 + lrow) * ldb);
    } else {
        gBf = (const float4*)(Bf + (size_t)(n0 + lrow) * ldb);
    }

    const int a_row = (lane & 7) + ((lane >> 3) & 1) * 8;
    const int a_cb  = (lane >> 4) * 16;
    const int ll    = lane & 15;
    const int b_row = ll & 7;
    const int b_cb  = (ll >> 3) * 16;

    float acc[4][4][4];
#pragma unroll
    for (int i = 0; i < 4; i++)
#pragma unroll
        for (int j = 0; j < 4; j++)
#pragma unroll
            for (int r = 0; r < 4; r++) acc[i][j][r] = 0.f;

    const int nch = Kd >> 5;
    float4 ra[4], rbf[4];
    uint4 rbh[2], rbl[2];

#define HG_LOAD(cc) do {                                                    \
        _Pragma("unroll")                                                   \
        for (int i = 0; i < 4; i++) ra[i] = gA[((cc) << 3) + seg * 4 + i];  \
        if (BSPLIT) {                                                       \
            _Pragma("unroll")                                               \
            for (int i = 0; i < 2; i++) {                                   \
                rbh[i] = gBh[((cc) << 2) + seg * 2 + i];                    \
                rbl[i] = gBl[((cc) << 2) + seg * 2 + i];                    \
            }                                                               \
        } else {                                                            \
            _Pragma("unroll")                                               \
            for (int i = 0; i < 4; i++) rbf[i] = gBf[((cc) << 3) + seg * 4 + i]; \
        }                                                                   \
    } while (0)

#define HG_STORE(cc) do {                                                   \
        char* st = smc + ((cc) & 1) * STAGE_B;                              \
        _Pragma("unroll")                                                   \
        for (int i = 0; i < 4; i++) {                                       \
            int f4 = seg * 4 + i;                                           \
            uint32_t h01, h23, l01, l23;                                    \
            cvt_hilo(ra[i].x, ra[i].y, h01, l01);                           \
            cvt_hilo(ra[i].z, ra[i].w, h23, l23);                           \
            int off = lrow * ROWB + f4 * 8;                                 \
            *(uint2*)(st + off)          = make_uint2(h01, h23);            \
            *(uint2*)(st + TILE_B + off) = make_uint2(l01, l23);            \
        }                                                                   \
        if (BSPLIT) {                                                       \
            int off = lrow * ROWB + seg * 32;                               \
            *(uint4*)(st + 2 * TILE_B + off)      = rbh[0];                 \
            *(uint4*)(st + 2 * TILE_B + off + 16) = rbh[1];                 \
            *(uint4*)(st + 3 * TILE_B + off)      = rbl[0];                 \
            *(uint4*)(st + 3 * TILE_B + off + 16) = rbl[1];                 \
        } else {                                                            \
            _Pragma("unroll")                                               \
            for (int i = 0; i < 4; i++) {                                   \
                int f4 = seg * 4 + i;                                       \
                uint32_t h01, h23, l01, l23;                                \
                cvt_hilo(rbf[i].x, rbf[i].y, h01, l01);                     \
                cvt_hilo(rbf[i].z, rbf[i].w, h23, l23);                     \
                int off = lrow * ROWB + f4 * 8;                             \
                *(uint2*)(st + 2 * TILE_B + off) = make_uint2(h01, h23);    \
                *(uint2*)(st + 3 * TILE_B + off) = make_uint2(l01, l23);    \
            }                                                               \
        }                                                                   \
    } while (0)

    HG_LOAD(0);
    HG_STORE(0);
    __syncthreads();

    for (int c = 0; c < nch; c++) {
        if (c + 1 < nch) HG_LOAD(c + 1);
        const uint32_t sb = sbase + (c & 1) * STAGE_B;
#pragma unroll
        for (int ks = 0; ks < 2; ks++) {
            const int kb = ks * 32;
            uint32_t ahi4[4][4], alo4[4][4];
#pragma unroll
            for (int mf = 0; mf < 4; mf++) {
                uint32_t ad = sb + (wm + mf * 16 + a_row) * ROWB + kb + a_cb;
                ldsm4(ahi4[mf], ad);
                ldsm4(alo4[mf], ad + TILE_B);
            }
            uint32_t bhi2[4][2], blo2[4][2];
#pragma unroll
            for (int nf = 0; nf < 4; nf++) {
                uint32_t bd = sb + 2 * TILE_B + (wn + nf * 8 + b_row) * ROWB + kb + b_cb;
                ldsm2(bhi2[nf], bd);
                ldsm2(blo2[nf], bd + TILE_B);
            }
#pragma unroll
            for (int mf = 0; mf < 4; mf++)
#pragma unroll
                for (int nf = 0; nf < 4; nf++) {
                    mma16816(acc[mf][nf], ahi4[mf], bhi2[nf]);
                    mma16816(acc[mf][nf], ahi4[mf], blo2[nf]);
                    mma16816(acc[mf][nf], alo4[mf], bhi2[nf]);
                }
        }
        __syncthreads();
        if (c + 1 < nch) {
            HG_STORE(c + 1);
            __syncthreads();
        }
    }
#undef HG_LOAD
#undef HG_STORE

    // epilogue
#pragma unroll
    for (int mf = 0; mf < 4; mf++) {
        int rbase = m0 + wm + mf * 16 + (lane >> 2);
#pragma unroll
        for (int nf = 0; nf < 4; nf++) {
            int cb = n0c + wn + nf * 8 + (lane & 3) * 2;
#pragma unroll
            for (int hlf = 0; hlf < 2; hlf++) {
                int row = rbase + hlf * 8;
                float vx = acc[mf][nf][hlf * 2];
                float vy = acc[mf][nf][hlf * 2 + 1];
                if (mode == 1) {
                    const float* ap = Add + (size_t)row * ldc + cb;
                    vx += ap[0]; vy += ap[1];
                }
                if (mode == 2) { vx = gelu_tanh(vx); vy = gelu_tanh(vy); }
                *(float2*)&C[(size_t)row * ldc + cb] = make_float2(vx, vy);
            }
        }
    }
}

// ---- wrappers -------------------------------------------------------------
// generic B-split GEMM
__global__ void __launch_bounds__(256) k_hg(
    const float* Af, int lda, const bf16* Bhi, const bf16* Blo, int ldb,
    float* C, const float* Add, int ldc, int Kd, int mode)
{
    hg_body<1>(Af, lda, nullptr, Bhi, Blo, ldb, C, Add, ldc,
               Kd, blockIdx.y * 128, blockIdx.x * 128, blockIdx.x * 128, mode);
}

// fused QKV: B rows [0,6144) of concatenated WqkvT; route output
__global__ void __launch_bounds__(256) k_hg_qkv() {
    int n0 = blockIdx.x * 128;
    int which = n0 >> 11;
    int n0c = n0 & 2047;
    float* C = (which == 0) ? g_q : (which == 1) ? g_k : g_v;
    hg_body<1>(g_h1, Dd, nullptr, g_WqkvThi, g_WqkvTlo, Dd, C, nullptr, Dd,
               Dd, blockIdx.y * 128, n0, n0c, 0);
}

__global__ void __launch_bounds__(256) k_hg_scores() {
    if (blockIdx.x * 128 > blockIdx.y * 128 + 127) return;
    int z = blockIdx.z;
    int b = z >> 4, h = z & 15;
    size_t qo = (size_t)b * KK * Dd + (size_t)h * HD;
    hg_body<0>(g_q + qo, Dd, g_k + qo, nullptr, nullptr, Dd,
               g_scores + (size_t)z * KK * KK, nullptr, KK,
               HD, blockIdx.y * 128, blockIdx.x * 128, blockIdx.x * 128, 0);
}

__global__ void __launch_bounds__(256) k_hg_av() {
    int z = blockIdx.z;
    int b = z >> 4, h = z & 15;
    size_t po = (size_t)z * KK * KK;
    size_t vo = (size_t)z * HD * KK;
    size_t co = (size_t)b * KK * Dd + (size_t)h * HD;
    int Keff = (blockIdx.y + 1) * 128;            // causal: probs zero beyond
    hg_body<1>(g_scores + po, KK, nullptr, g_vThi + vo, g_vTlo + vo, KK,
               g_att + co, nullptr, Dd, Keff, blockIdx.y * 128, 0, 0, 0);
}

// ----------------------------------------------------------------------------
// Weight transpose + split
// ----------------------------------------------------------------------------
__global__ void k_tsplit(const float* __restrict__ W, bf16* __restrict__ Thi,
                         bf16* __restrict__ Tlo, int Kd, int Nd) {
    __shared__ float t[32][33];
    int k0 = blockIdx.y * 32, n0 = blockIdx.x * 32;
    int x = threadIdx.x, y = threadIdx.y;
#pragma unroll
    for (int i = 0; i < 32; i += 8)
        t[y + i][x] = W[(size_t)(k0 + y + i) * Nd + n0 + x];
    __syncthreads();
#pragma unroll
    for (int i = 0; i < 32; i += 8)
        store_hilo(Thi, Tlo, (size_t)(n0 + y + i) * Kd + k0 + x, t[x][y + i]);
}

__global__ void k_vt() {   // g_v [b][tok][h][d] -> vThi/lo [b*H+h][d][tok]
    __shared__ float t[32][33];
    int z = blockIdx.z, b = z >> 4, h = z & 15;
    int tok0 = blockIdx.x * 32, d0 = blockIdx.y * 32;
    int x = threadIdx.x, y = threadIdx.y;
#pragma unroll
    for (int i = 0; i < 32; i += 8)
        t[y + i][x] = g_v[(size_t)b * KK * Dd + (size_t)(tok0 + y + i) * Dd + h * HD + d0 + x];
    __syncthreads();
#pragma unroll
    for (int i = 0; i < 32; i += 8)
        store_hilo(g_vThi, g_vTlo,
                   (size_t)z * HD * KK + (size_t)(d0 + y + i) * KK + tok0 + x,
                   t[x][y + i]);
}

// ----------------------------------------------------------------------------
// Router / select / gather
// ----------------------------------------------------------------------------
__global__ void k_router(const float* __restrict__ hidden, const float* __restrict__ rw) {
    int wid  = (blockIdx.x * blockDim.x + threadIdx.x) >> 5;
    int lane = threadIdx.x & 31;
    if (wid >= Bb * Ss) return;
    const float4* x  = (const float4*)(hidden + (size_t)wid * Dd);
    const float4* r4 = (const float4*)rw;
    float s = 0.f;
#pragma unroll 4
    for (int i = lane; i < Dd / 4; i += 32) {
        float4 a = x[i], b = r4[i];
        s += a.x * b.x + a.y * b.y + a.z * b.z + a.w * b.w;
    }
    s = warpReduceSum(s);
    if (lane == 0) g_weights[wid] = 1.f / (1.f + expf(-s));
}

__global__ void k_select(const int* __restrict__ pos_ids) {
    __shared__ float w[Ss];
    __shared__ unsigned char sel[Ss];
    int b = blockIdx.x;
    for (int s = threadIdx.x; s < Ss; s += blockDim.x) w[s] = g_weights[b * Ss + s];
    __syncthreads();
    for (int s = threadIdx.x; s < Ss; s += blockDim.x) {
        float ws = w[s];
        int r = 0;
        for (int t = 0; t < Ss; t++) {
            float wt = w[t];
            r += (wt > ws) || (wt == ws && t < s);
        }
        sel[s] = (r < KK) ? 1 : 0;
    }
    __syncthreads();
    for (int s = threadIdx.x; s < Ss; s += blockDim.x) {
        if (sel[s]) {
            int j = 0;
            for (int t = 0; t < s; t++) j += sel[t];
            g_kidx[b * KK + j] = s;
            g_kpos[b * KK + j] = pos_ids[s];
        }
    }
}

__global__ void k_gather_rms1(const float* __restrict__ hidden, const float* __restrict__ ln1w) {
    int t = blockIdx.x;
    int b = t >> 10;
    int s = g_kidx[t];
    const float* src = hidden + ((size_t)(b * Ss + s)) * Dd;
    float* xdst = g_X  + (size_t)t * Dd;
    float* hdst = g_h1 + (size_t)t * Dd;
    int c0 = threadIdx.x * 8;
    float loc[8];
    *(float4*)&loc[0] = *(const float4*)&src[c0];
    *(float4*)&loc[4] = *(const float4*)&src[c0 + 4];
    float ss = 0.f;
#pragma unroll
    for (int i = 0; i < 8; i++) ss += loc[i] * loc[i];
    ss = blockReduceSum(ss);
    float r = rsqrtf(ss * (1.f / Dd) + EPSf);
    *(float4*)&xdst[c0]     = *(float4*)&loc[0];
    *(float4*)&xdst[c0 + 4] = *(float4*)&loc[4];
    float o[8];
#pragma unroll
    for (int i = 0; i < 8; i++) o[i] = loc[i] * r * ln1w[c0 + i];
    *(float4*)&hdst[c0]     = *(float4*)&o[0];
    *(float4*)&hdst[c0 + 4] = *(float4*)&o[4];
}

// ----------------------------------------------------------------------------
// RoPE (fp32 in-place, float2 vectorized)
// ----------------------------------------------------------------------------
__global__ void k_rope() {
    int t = blockIdx.x * blockDim.x + threadIdx.x;   // MTOT * H * 32
    if (t >= MTOT * Hh * 32) return;
    int dp  = (t & 31) * 2;
    int th  = t >> 5;
    int h   = th & 15;
    int tok = th >> 4;
    int pos = g_kpos[tok];
    float fp = (float)pos;
    float f0 = expf((float)dp       * (-9.210340371976184f / 64.f));
    float f1 = expf((float)(dp + 1) * (-9.210340371976184f / 64.f));
    float c0 = cosf(fp * f0), s0 = sinf(fp * f0);
    float c1 = cosf(fp * f1), s1 = sinf(fp * f1);
    size_t base = (size_t)tok * Dd + h * HD + dp;
    float2 q1 = *(float2*)&g_q[base];
    float2 q2 = *(float2*)&g_q[base + HALF];
    *(float2*)&g_q[base]        = make_float2(q1.x * c0 - q2.x * s0, q1.y * c1 - q2.y * s1);
    *(float2*)&g_q[base + HALF] = make_float2(q2.x * c0 + q1.x * s0, q2.y * c1 + q1.y * s1);
    float2 k1 = *(float2*)&g_k[base];
    float2 k2 = *(float2*)&g_k[base + HALF];
    *(float2*)&g_k[base]        = make_float2(k1.x * c0 - k2.x * s0, k1.y * c1 - k2.y * s1);
    *(float2*)&g_k[base + HALF] = make_float2(k2.x * c0 + k1.x * s0, k2.y * c1 + k1.y * s1);
}

// ----------------------------------------------------------------------------
// Softmax (fp32 in place, vectorized; zeros above diagonal)
// ----------------------------------------------------------------------------
__global__ void k_softmax() {
    int row = blockIdx.x;
    int q = row & (KK - 1);
    float* r = g_scores + (size_t)row * KK;
    int n = q + 1;
    int c0 = threadIdx.x * 8;
    float v[8];
    *(float4*)&v[0] = *(const float4*)&r[c0];
    *(float4*)&v[4] = *(const float4*)&r[c0 + 4];
    float m = -FLT_MAX;
#pragma unroll
    for (int i = 0; i < 8; i++)
        if (c0 + i < n) m = fmaxf(m, v[i]);
    m = blockReduceMax(m);
    float e[8];
    float sum = 0.f;
#pragma unroll
    for (int i = 0; i < 8; i++) {
        e[i] = (c0 + i < n) ? expf(SM_SCALE * (v[i] - m)) : 0.f;
        sum += e[i];
    }
    sum = blockReduceSum(sum);
    float inv = 1.f / sum;
#pragma unroll
    for (int i = 0; i < 8; i++) e[i] *= inv;
    *(float4*)&r[c0]     = *(float4*)&e[0];
    *(float4*)&r[c0 + 4] = *(float4*)&e[4];
}

// ----------------------------------------------------------------------------
// h2 = X + ao ; rmsnorm -> fp32
// ----------------------------------------------------------------------------
__global__ void k_h2rms(const float* __restrict__ ln2w) {
    int t = blockIdx.x;
    const float* xa = g_X  + (size_t)t * Dd;
    const float* ao = g_ao + (size_t)t * Dd;
    float* dst = g_h2n + (size_t)t * Dd;
    int c0 = threadIdx.x * 8;
    float loc[8];
#pragma unroll
    for (int i = 0; i < 8; i += 4) {
        float4 a = *(const float4*)&xa[c0 + i];
        float4 b = *(const float4*)&ao[c0 + i];
        loc[i] = a.x + b.x; loc[i + 1] = a.y + b.y;
        loc[i + 2] = a.z + b.z; loc[i + 3] = a.w + b.w;
    }
    float ss = 0.f;
#pragma unroll
    for (int i = 0; i < 8; i++) ss += loc[i] * loc[i];
    ss = blockReduceSum(ss);
    float r = rsqrtf(ss * (1.f / Dd) + EPSf);
    float o[8];
#pragma unroll
    for (int i = 0; i < 8; i++) o[i] = loc[i] * r * ln2w[c0 + i];
    *(float4*)&dst[c0]     = *(float4*)&o[0];
    *(float4*)&dst[c0 + 4] = *(float4*)&o[4];
}

__global__ void k_outscale(const float* __restrict__ hidden, float* __restrict__ out) {
    size_t total4 = (size_t)Bb * Ss * Dd / 4;
    for (size_t i = (size_t)blockIdx.x * blockDim.x + threadIdx.x; i < total4;
         i += (size_t)gridDim.x * blockDim.x) {
        size_t tok = (i * 4) >> 11;
        float sc = g_weights[tok];
        float4 h = ((const float4*)hidden)[i];
        h.x *= sc; h.y *= sc; h.z *= sc; h.w *= sc;
        ((float4*)out)[i] = h;
    }
}

__global__ void k_scatter(float* __restrict__ out) {
    int t = blockIdx.x;
    int b = t >> 10;
    int s = g_kidx[t];
    int tok = b * Ss + s;
    float sc = g_weights[tok];
    float*       o  = out     + (size_t)tok * Dd;
    const float* dl = g_delta + (size_t)t * Dd;
    const float* xk = g_X     + (size_t)t * Dd;
    for (int c = threadIdx.x * 4; c < Dd; c += blockDim.x * 4) {
        float4 d4 = *(const float4*)&dl[c];
        float4 x4 = *(const float4*)&xk[c];
        *(float4*)&o[c] = make_float4(d4.x * sc + x4.x, d4.y * sc + x4.y,
                                      d4.z * sc + x4.z, d4.w * sc + x4.w);
    }
}

// ----------------------------------------------------------------------------
// Launch
// ----------------------------------------------------------------------------
extern "C" void kernel_launch(void* const* d_in, const int* in_sizes, int n_in,
                              void* d_out, int out_size) {
    const float* hidden   = (const float*)d_in[0];
    const int*   pos_ids  = (const int*)d_in[1];
    const float* router_w = (const float*)d_in[4];
    const float* ln1w     = (const float*)d_in[5];
    const float* ln2w     = (const float*)d_in[6];
    const float* Wq       = (const float*)d_in[7];
    const float* Wk       = (const float*)d_in[8];
    const float* Wv       = (const float*)d_in[9];
    const float* Wo       = (const float*)d_in[10];
    const float* W1       = (const float*)d_in[11];
    const float* W2       = (const float*)d_in[12];
    float* out = (float*)d_out;

    cudaFuncSetAttribute(k_hg,        cudaFuncAttributeMaxDynamicSharedMemorySize, HG_SMEM);
    cudaFuncSetAttribute(k_hg_qkv,    cudaFuncAttributeMaxDynamicSharedMemorySize, HG_SMEM);
    cudaFuncSetAttribute(k_hg_scores, cudaFuncAttributeMaxDynamicSharedMemorySize, HG_SMEM);
    cudaFuncSetAttribute(k_hg_av,     cudaFuncAttributeMaxDynamicSharedMemorySize, HG_SMEM);

#define SYM(p, g) cudaGetSymbolAddress((void**)&p, g)
    bf16 *WqkvThi, *WqkvTlo, *WoThi, *WoTlo, *W1Thi, *W1Tlo, *W2Thi, *W2Tlo;
    float *h1, *att, *ao, *h2n, *ffh, *dlt;
    SYM(WqkvThi, g_WqkvThi); SYM(WqkvTlo, g_WqkvTlo);
    SYM(WoThi, g_WoThi); SYM(WoTlo, g_WoTlo);
    SYM(W1Thi, g_W1Thi); SYM(W1Tlo, g_W1Tlo);
    SYM(W2Thi, g_W2Thi); SYM(W2Tlo, g_W2Tlo);
    SYM(h1, g_h1); SYM(att, g_att); SYM(ao, g_ao);
    SYM(h2n, g_h2n); SYM(ffh, g_ffh); SYM(dlt, g_delta);
#undef SYM

    dim3 tb(32, 8);
    const size_t DD = (size_t)Dd * Dd;
    k_tsplit<<<dim3(Dd / 32, Dd / 32), tb>>>(Wq, WqkvThi,          WqkvTlo,          Dd, Dd);
    k_tsplit<<<dim3(Dd / 32, Dd / 32), tb>>>(Wk, WqkvThi + DD,     WqkvTlo + DD,     Dd, Dd);
    k_tsplit<<<dim3(Dd / 32, Dd / 32), tb>>>(Wv, WqkvThi + 2 * DD, WqkvTlo + 2 * DD, Dd, Dd);
    k_tsplit<<<dim3(Dd / 32, Dd / 32), tb>>>(Wo, WoThi, WoTlo, Dd, Dd);
    k_tsplit<<<dim3(FFd / 32, Dd / 32), tb>>>(W1, W1Thi, W1Tlo, Dd, FFd);
    k_tsplit<<<dim3(Dd / 32, FFd / 32), tb>>>(W2, W2Thi, W2Tlo, FFd, Dd);

    k_router<<<(Bb * Ss) / 8, 256>>>(hidden, router_w);
    k_select<<<Bb, 1024>>>(pos_ids);
    k_gather_rms1<<<MTOT, 256>>>(hidden, ln1w);

    // fused QKV
    k_hg_qkv<<<dim3(3 * Dd / 128, MTOT / 128), 256, HG_SMEM>>>();

    k_rope<<<(MTOT * Hh * 32 + 255) / 256, 256>>>();
    k_vt<<<dim3(KK / 32, HD / 32, BH), tb>>>();
    k_hg_scores<<<dim3(KK / 128, KK / 128, BH), 256, HG_SMEM>>>();
    k_softmax<<<BH * KK, 128>>>();
    k_hg_av<<<dim3(1, KK / 128, BH), 256, HG_SMEM>>>();

    dim3 gD(Dd / 128, MTOT / 128);
    k_hg<<<gD, 256, HG_SMEM>>>(att, Dd, WoThi, WoTlo, Dd, ao, nullptr, Dd, Dd, 0);
    k_h2rms<<<MTOT, 256>>>(ln2w);
    k_hg<<<dim3(FFd / 128, MTOT / 128), 256, HG_SMEM>>>(
        h2n, Dd, W1Thi, W1Tlo, Dd, ffh, nullptr, FFd, Dd, 2);
    k_hg<<<gD, 256, HG_SMEM>>>(ffh, FFd, W2Thi, W2Tlo, FFd, dlt, ao, Dd, FFd, 1);

    k_outscale<<<8192, 256>>>(hidden, out);
    k_scatter<<<MTOT, 256>>>(out);
}

// round 13
// speedup vs baseline: 1.5577x; 1.5577x over previous
#include <cuda_runtime.h>
#include <cuda_bf16.h>
#include <math.h>
#include <float.h>
#include <stdint.h>

#define Dd   2048
#define Hh   16
#define HD   128
#define HALF 64
#define FFd  8192
#define Bb   4
#define Ss   2048
#define KK   1024
#define MTOT (Bb * KK)
#define BH   (Bb * Hh)
#define EPSf 1e-6f
#define SM_SCALE 0.08838834764831843f

// ----------------------------------------------------------------------------
// Scratch (device globals)
// ----------------------------------------------------------------------------
__device__ float g_weights[Bb * Ss];
__device__ int   g_kidx[MTOT];
__device__ int   g_kpos[MTOT];
__device__ float g_X   [(size_t)MTOT * Dd];
__device__ float g_h1  [(size_t)MTOT * Dd];
__device__ float g_q   [(size_t)MTOT * Dd];
__device__ float g_k   [(size_t)MTOT * Dd];
__device__ float g_v   [(size_t)MTOT * Dd];
__device__ float g_vT  [(size_t)BH * HD * KK];        // per-head V^T [d][tok]
__device__ float g_scores[(size_t)BH * KK * KK];
__device__ float g_att [(size_t)MTOT * Dd];
__device__ float g_ao  [(size_t)MTOT * Dd];
__device__ float g_h2n [(size_t)MTOT * Dd];
__device__ float g_ffh [(size_t)MTOT * FFd];
__device__ float g_delta[(size_t)MTOT * Dd];
// transposed weights [N, K] fp32
__device__ float g_WqT[(size_t)Dd * Dd];
__device__ float g_WkT[(size_t)Dd * Dd];
__device__ float g_WvT[(size_t)Dd * Dd];
__device__ float g_WoT[(size_t)Dd * Dd];
__device__ float g_W1T[(size_t)FFd * Dd];
__device__ float g_W2T[(size_t)Dd * FFd];

// ----------------------------------------------------------------------------
// Helpers
// ----------------------------------------------------------------------------
__device__ __forceinline__ float warpReduceSum(float v) {
#pragma unroll
    for (int o = 16; o > 0; o >>= 1) v += __shfl_xor_sync(0xffffffffu, v, o);
    return v;
}
__device__ __forceinline__ float warpReduceMax(float v) {
#pragma unroll
    for (int o = 16; o > 0; o >>= 1) v = fmaxf(v, __shfl_xor_sync(0xffffffffu, v, o));
    return v;
}
__device__ float blockReduceSum(float v) {
    __shared__ float sm[8];
    __shared__ float res;
    int lane = threadIdx.x & 31, w = threadIdx.x >> 5;
    int nw = (blockDim.x + 31) >> 5;
    v = warpReduceSum(v);
    if (lane == 0) sm[w] = v;
    __syncthreads();
    if (w == 0) {
        float x = (lane < nw) ? sm[lane] : 0.f;
        x = warpReduceSum(x);
        if (lane == 0) res = x;
    }
    __syncthreads();
    return res;
}
__device__ float blockReduceMax(float v) {
    __shared__ float sm[8];
    __shared__ float res;
    int lane = threadIdx.x & 31, w = threadIdx.x >> 5;
    int nw = (blockDim.x + 31) >> 5;
    v = warpReduceMax(v);
    if (lane == 0) sm[w] = v;
    __syncthreads();
    if (w == 0) {
        float x = (lane < nw) ? sm[lane] : -FLT_MAX;
        x = warpReduceMax(x);
        if (lane == 0) res = x;
    }
    __syncthreads();
    return res;
}
__device__ __forceinline__ float gelu_tanh(float x) {
    float x3 = x * x * x;
    float t = tanhf(0.7978845608028654f * (x + 0.044715f * x3));
    return 0.5f * x * (1.f + t);
}
__device__ __forceinline__ uint32_t smem_u32(const void* p) {
    uint32_t a;
    asm("{ .reg .u64 t; cvta.to.shared.u64 t, %1; cvt.u32.u64 %0, t; }" : "=r"(a) : "l"(p));
    return a;
}
// fp32 pair -> bf16x2 hi + bf16x2 lo
__device__ __forceinline__ void cvt_hilo(float a, float b, uint32_t& h, uint32_t& l) {
    __nv_bfloat162 hv = __floats2bfloat162_rn(a, b);
    h = *reinterpret_cast<uint32_t*>(&hv);
    float fa = __uint_as_float(h << 16);
    float fb = __uint_as_float(h & 0xffff0000u);
    __nv_bfloat162 lv = __floats2bfloat162_rn(a - fa, b - fb);
    l = *reinterpret_cast<uint32_t*>(&lv);
}

// ----------------------------------------------------------------------------
// HMMA primitives (base PTX, works on plain sm_103 target)
// ----------------------------------------------------------------------------
__device__ __forceinline__ void ldsm4(uint32_t* r, uint32_t a) {
    asm volatile("ldmatrix.sync.aligned.m8n8.x4.shared.b16 {%0,%1,%2,%3}, [%4];"
        : "=r"(r[0]), "=r"(r[1]), "=r"(r[2]), "=r"(r[3]) : "r"(a));
}
__device__ __forceinline__ void ldsm2(uint32_t* r, uint32_t a) {
    asm volatile("ldmatrix.sync.aligned.m8n8.x2.shared.b16 {%0,%1}, [%2];"
        : "=r"(r[0]), "=r"(r[1]) : "r"(a));
}
__device__ __forceinline__ void mma16816(float* c, const uint32_t* a, const uint32_t* b) {
    asm volatile("mma.sync.aligned.m16n8k16.row.col.f32.bf16.bf16.f32 "
        "{%0,%1,%2,%3}, {%4,%5,%6,%7}, {%8,%9}, {%0,%1,%2,%3};"
        : "+f"(c[0]), "+f"(c[1]), "+f"(c[2]), "+f"(c[3])
        : "r"(a[0]), "r"(a[1]), "r"(a[2]), "r"(a[3]), "r"(b[0]), "r"(b[1]));
}

// SMEM layout per stage: Ahi[128][40] Alo Bhi Blo bf16, row stride 80B
#define ROWB   80
#define TILE_B 10240
#define STAGE_B 40960
#define HG_SMEM (2 * STAGE_B)

// ----------------------------------------------------------------------------
// HMMA split-bf16 GEMM body: C[128,128 tile] = A[M,K] @ Bt[N,K]^T (+Add, act)
// 256 threads = 8 warps (2x4), warp tile 64x32, BK=32, double buffer.
// (Proven R6 schedule — do not restructure.)
// ----------------------------------------------------------------------------
__device__ __forceinline__ void hgemm_body(
    const float* __restrict__ A, int lda,
    const float* __restrict__ Bt, int ldb,
    float* __restrict__ C, int ldc,
    const float* __restrict__ Add,
    int Kd, int act)
{
    extern __shared__ char smc[];
    const uint32_t sbase = smem_u32(smc);
    const int tid  = threadIdx.x;
    const int m0   = blockIdx.y * 128, n0 = blockIdx.x * 128;
    const int wid  = tid >> 5, lane = tid & 31;
    const int wm   = (wid >> 2) * 64;
    const int wn   = (wid & 3) * 32;
    const int lrow = tid >> 1;
    const int lf4  = (tid & 1) * 4;

    const float4* gA = (const float4*)(A  + (size_t)(m0 + lrow) * lda);
    const float4* gB = (const float4*)(Bt + (size_t)(n0 + lrow) * ldb);

    float acc[4][4][4];
#pragma unroll
    for (int i = 0; i < 4; i++)
#pragma unroll
        for (int j = 0; j < 4; j++)
#pragma unroll
            for (int r = 0; r < 4; r++) acc[i][j][r] = 0.f;

    const int a_row = (lane & 7) + ((lane >> 3) & 1) * 8;
    const int a_cb  = (lane >> 4) * 16;
    const int ll    = lane & 15;
    const int b_row = ll & 7;
    const int b_cb  = (ll >> 3) * 16;

    float4 ra[4], rb[4];
    const int nch = Kd >> 5;

    // prefetch + store chunk 0
#pragma unroll
    for (int i = 0; i < 4; i++) { ra[i] = gA[lf4 + i]; rb[i] = gB[lf4 + i]; }
    {
        char* st = smc;
#pragma unroll
        for (int i = 0; i < 4; i++) {
            int f4 = lf4 + i;
            uint32_t h01, h23, l01, l23;
            cvt_hilo(ra[i].x, ra[i].y, h01, l01);
            cvt_hilo(ra[i].z, ra[i].w, h23, l23);
            int off = lrow * ROWB + f4 * 8;
            *(uint2*)(st + off)          = make_uint2(h01, h23);
            *(uint2*)(st + TILE_B + off) = make_uint2(l01, l23);
            cvt_hilo(rb[i].x, rb[i].y, h01, l01);
            cvt_hilo(rb[i].z, rb[i].w, h23, l23);
            *(uint2*)(st + 2 * TILE_B + off) = make_uint2(h01, h23);
            *(uint2*)(st + 3 * TILE_B + off) = make_uint2(l01, l23);
        }
    }
    __syncthreads();

    for (int c = 0; c < nch; c++) {
        const int s = c & 1;
        if (c + 1 < nch) {
            int fb = ((c + 1) << 3) + lf4;
#pragma unroll
            for (int i = 0; i < 4; i++) { ra[i] = gA[fb + i]; rb[i] = gB[fb + i]; }
        }
        // compute from stage s
        const uint32_t sb = sbase + s * STAGE_B;
#pragma unroll
        for (int ks = 0; ks < 2; ks++) {
            const int kb = ks * 32;
            uint32_t ahi[4][4], alo[4][4];
#pragma unroll
            for (int mf = 0; mf < 4; mf++) {
                uint32_t ad = sb + (wm + mf * 16 + a_row) * ROWB + kb + a_cb;
                ldsm4(ahi[mf], ad);
                ldsm4(alo[mf], ad + TILE_B);
            }
            uint32_t bhi[4][2], blo[4][2];
#pragma unroll
            for (int nf = 0; nf < 4; nf++) {
                uint32_t bd = sb + 2 * TILE_B + (wn + nf * 8 + b_row) * ROWB + kb + b_cb;
                ldsm2(bhi[nf], bd);
                ldsm2(blo[nf], bd + TILE_B);
            }
#pragma unroll
            for (int mf = 0; mf < 4; mf++)
#pragma unroll
                for (int nf = 0; nf < 4; nf++) {
                    mma16816(acc[mf][nf], ahi[mf], bhi[nf]);
                    mma16816(acc[mf][nf], ahi[mf], blo[nf]);
                    mma16816(acc[mf][nf], alo[mf], bhi[nf]);
                }
        }
        __syncthreads();
        if (c + 1 < nch) {
            char* st = smc + (s ^ 1) * STAGE_B;
#pragma unroll
            for (int i = 0; i < 4; i++) {
                int f4 = lf4 + i;
                uint32_t h01, h23, l01, l23;
                cvt_hilo(ra[i].x, ra[i].y, h01, l01);
                cvt_hilo(ra[i].z, ra[i].w, h23, l23);
                int off = lrow * ROWB + f4 * 8;
                *(uint2*)(st + off)          = make_uint2(h01, h23);
                *(uint2*)(st + TILE_B + off) = make_uint2(l01, l23);
                cvt_hilo(rb[i].x, rb[i].y, h01, l01);
                cvt_hilo(rb[i].z, rb[i].w, h23, l23);
                *(uint2*)(st + 2 * TILE_B + off) = make_uint2(h01, h23);
                *(uint2*)(st + 3 * TILE_B + off) = make_uint2(l01, l23);
            }
            __syncthreads();
        }
    }

    // epilogue
#pragma unroll
    for (int mf = 0; mf < 4; mf++) {
        int rbase = m0 + wm + mf * 16 + (lane >> 2);
#pragma unroll
        for (int nf = 0; nf < 4; nf++) {
            int cb = n0 + wn + nf * 8 + (lane & 3) * 2;
#pragma unroll
            for (int hlf = 0; hlf < 2; hlf++) {
                int row = rbase + hlf * 8;
                float vx = acc[mf][nf][hlf * 2];
                float vy = acc[mf][nf][hlf * 2 + 1];
                if (Add) {
                    const float* ap = Add + (size_t)row * ldc + cb;
                    vx += ap[0]; vy += ap[1];
                }
                if (act == 1) { vx = gelu_tanh(vx); vy = gelu_tanh(vy); }
                float2* cp = (float2*)(C + (size_t)row * ldc + cb);
                *cp = make_float2(vx, vy);
            }
        }
    }
}

// Wrappers
__global__ void __launch_bounds__(256) k_hg_main(
    const float* __restrict__ A, const float* __restrict__ Bt,
    float* __restrict__ C, const float* __restrict__ Add,
    int Kd, int ldc, int act)
{
    hgemm_body(A, Kd, Bt, Kd, C, ldc, Add, Kd, act);
}

__global__ void __launch_bounds__(256) k_hg_scores() {
    if (blockIdx.x * 128 > blockIdx.y * 128 + 127) return;  // fully masked tile
    int z = blockIdx.z;
    int b = z >> 4, h = z & 15;
    const float* A  = g_q + (size_t)b * KK * Dd + (size_t)h * HD;
    const float* Bt = g_k + (size_t)b * KK * Dd + (size_t)h * HD;
    float* C = g_scores + (size_t)z * KK * KK;
    hgemm_body(A, Dd, Bt, Dd, C, KK, nullptr, HD, 0);
}

__global__ void __launch_bounds__(256) k_hg_av() {
    int z = blockIdx.z;
    int b = z >> 4, h = z & 15;
    const float* A  = g_scores + (size_t)z * KK * KK;
    const float* Bt = g_vT + (size_t)z * HD * KK;
    float* C = g_att + (size_t)b * KK * Dd + (size_t)h * HD;
    int Keff = (blockIdx.y + 1) * 128;   // causal: probs are exactly 0 beyond
    hgemm_body(A, KK, Bt, KK, C, Dd, nullptr, Keff, 0);
}

// ----------------------------------------------------------------------------
// Transposes
// ----------------------------------------------------------------------------
__global__ void k_transpose(const float* __restrict__ W, float* __restrict__ WT,
                            int Kd, int Nd) {
    __shared__ float t[32][33];
    int k0 = blockIdx.y * 32, n0 = blockIdx.x * 32;
    int x = threadIdx.x, y = threadIdx.y;
#pragma unroll
    for (int i = 0; i < 32; i += 8)
        t[y + i][x] = W[(size_t)(k0 + y + i) * Nd + n0 + x];
    __syncthreads();
#pragma unroll
    for (int i = 0; i < 32; i += 8)
        WT[(size_t)(n0 + y + i) * Kd + k0 + x] = t[x][y + i];
}

__global__ void k_vt() {   // g_v [b][tok][h][d] -> g_vT [b*H+h][d][tok]
    __shared__ float t[32][33];
    int z = blockIdx.z, b = z >> 4, h = z & 15;
    int tok0 = blockIdx.x * 32, d0 = blockIdx.y * 32;
    int x = threadIdx.x, y = threadIdx.y;
#pragma unroll
    for (int i = 0; i < 32; i += 8)
        t[y + i][x] = g_v[(size_t)b * KK * Dd + (size_t)(tok0 + y + i) * Dd + h * HD + d0 + x];
    __syncthreads();
#pragma unroll
    for (int i = 0; i < 32; i += 8)
        g_vT[(size_t)z * HD * KK + (size_t)(d0 + y + i) * KK + tok0 + x] = t[x][y + i];
}

// ----------------------------------------------------------------------------
// Router / select / gather
// ----------------------------------------------------------------------------
__global__ void k_router(const float* __restrict__ hidden, const float* __restrict__ rw) {
    int wid  = (blockIdx.x * blockDim.x + threadIdx.x) >> 5;
    int lane = threadIdx.x & 31;
    if (wid >= Bb * Ss) return;
    const float4* x  = (const float4*)(hidden + (size_t)wid * Dd);
    const float4* r4 = (const float4*)rw;
    float s = 0.f;
#pragma unroll 4
    for (int i = lane; i < Dd / 4; i += 32) {
        float4 a = x[i], b = r4[i];
        s += a.x * b.x + a.y * b.y + a.z * b.z + a.w * b.w;
    }
    s = warpReduceSum(s);
    if (lane == 0) g_weights[wid] = 1.f / (1.f + expf(-s));
}

__global__ void k_select(const int* __restrict__ pos_ids) {
    __shared__ float w[Ss];
    __shared__ unsigned char sel[Ss];
    int b = blockIdx.x;
    for (int s = threadIdx.x; s < Ss; s += blockDim.x) w[s] = g_weights[b * Ss + s];
    __syncthreads();
    for (int s = threadIdx.x; s < Ss; s += blockDim.x) {
        float ws = w[s];
        int r = 0;
        for (int t = 0; t < Ss; t++) {
            float wt = w[t];
            r += (wt > ws) || (wt == ws && t < s);
        }
        sel[s] = (r < KK) ? 1 : 0;
    }
    __syncthreads();
    for (int s = threadIdx.x; s < Ss; s += blockDim.x) {
        if (sel[s]) {
            int j = 0;
            for (int t = 0; t < s; t++) j += sel[t];
            g_kidx[b * KK + j] = s;
            g_kpos[b * KK + j] = pos_ids[s];
        }
    }
}

// 256 threads/token; thread owns 8 consecutive columns -> vector accesses
__global__ void k_gather_rms1(const float* __restrict__ hidden, const float* __restrict__ ln1w) {
    int t = blockIdx.x;
    int b = t >> 10;
    int s = g_kidx[t];
    const float* src = hidden + ((size_t)(b * Ss + s)) * Dd;
    float* xdst = g_X  + (size_t)t * Dd;
    float* hdst = g_h1 + (size_t)t * Dd;
    int c0 = threadIdx.x * 8;
    float loc[8];
    *(float4*)&loc[0] = *(const float4*)&src[c0];
    *(float4*)&loc[4] = *(const float4*)&src[c0 + 4];
    float ss = 0.f;
#pragma unroll
    for (int i = 0; i < 8; i++) ss += loc[i] * loc[i];
    ss = blockReduceSum(ss);
    float r = rsqrtf(ss * (1.f / Dd) + EPSf);
    *(float4*)&xdst[c0]     = *(float4*)&loc[0];
    *(float4*)&xdst[c0 + 4] = *(float4*)&loc[4];
    float o[8];
#pragma unroll
    for (int i = 0; i < 8; i++) o[i] = loc[i] * r * ln1w[c0 + i];
    *(float4*)&hdst[c0]     = *(float4*)&o[0];
    *(float4*)&hdst[c0 + 4] = *(float4*)&o[4];
}

// ----------------------------------------------------------------------------
// RoPE (fp32 in-place, float2 vectorized)
// ----------------------------------------------------------------------------
__global__ void k_rope() {
    int t = blockIdx.x * blockDim.x + threadIdx.x;   // MTOT * H * 32
    if (t >= MTOT * Hh * 32) return;
    int dp  = (t & 31) * 2;
    int th  = t >> 5;
    int h   = th & 15;
    int tok = th >> 4;
    int pos = g_kpos[tok];
    float fp = (float)pos;
    float f0 = expf((float)dp       * (-9.210340371976184f / 64.f));
    float f1 = expf((float)(dp + 1) * (-9.210340371976184f / 64.f));
    float c0 = cosf(fp * f0), s0 = sinf(fp * f0);
    float c1 = cosf(fp * f1), s1 = sinf(fp * f1);
    size_t base = (size_t)tok * Dd + h * HD + dp;
    float2 q1 = *(float2*)&g_q[base];
    float2 q2 = *(float2*)&g_q[base + HALF];
    *(float2*)&g_q[base]        = make_float2(q1.x * c0 - q2.x * s0, q1.y * c1 - q2.y * s1);
    *(float2*)&g_q[base + HALF] = make_float2(q2.x * c0 + q1.x * s0, q2.y * c1 + q1.y * s1);
    float2 k1 = *(float2*)&g_k[base];
    float2 k2 = *(float2*)&g_k[base + HALF];
    *(float2*)&g_k[base]        = make_float2(k1.x * c0 - k2.x * s0, k1.y * c1 - k2.y * s1);
    *(float2*)&g_k[base + HALF] = make_float2(k2.x * c0 + k1.x * s0, k2.y * c1 + k1.y * s1);
}

// ----------------------------------------------------------------------------
// Softmax: 128 threads/row, thread owns 8 consecutive columns; fp32 in place
// ----------------------------------------------------------------------------
__global__ void k_softmax() {
    int row = blockIdx.x;
    int q = row & (KK - 1);
    float* r = g_scores + (size_t)row * KK;
    int n = q + 1;
    int c0 = threadIdx.x * 8;
    float v[8];
    *(float4*)&v[0] = *(const float4*)&r[c0];
    *(float4*)&v[4] = *(const float4*)&r[c0 + 4];
    float m = -FLT_MAX;
#pragma unroll
    for (int i = 0; i < 8; i++)
        if (c0 + i < n) m = fmaxf(m, v[i]);
    m = blockReduceMax(m);
    float e[8];
    float sum = 0.f;
#pragma unroll
    for (int i = 0; i < 8; i++) {
        e[i] = (c0 + i < n) ? expf(SM_SCALE * (v[i] - m)) : 0.f;
        sum += e[i];
    }
    sum = blockReduceSum(sum);
    float inv = 1.f / sum;
#pragma unroll
    for (int i = 0; i < 8; i++) e[i] *= inv;
    *(float4*)&r[c0]     = *(float4*)&e[0];
    *(float4*)&r[c0 + 4] = *(float4*)&e[4];
}

// ----------------------------------------------------------------------------
// h2 = X + ao ; rmsnorm -> fp32 (vectorized)
// ----------------------------------------------------------------------------
__global__ void k_h2rms(const float* __restrict__ ln2w) {
    int t = blockIdx.x;
    const float* xa = g_X  + (size_t)t * Dd;
    const float* ao = g_ao + (size_t)t * Dd;
    float* dst = g_h2n + (size_t)t * Dd;
    int c0 = threadIdx.x * 8;
    float loc[8];
#pragma unroll
    for (int i = 0; i < 8; i += 4) {
        float4 a = *(const float4*)&xa[c0 + i];
        float4 b = *(const float4*)&ao[c0 + i];
        loc[i] = a.x + b.x; loc[i + 1] = a.y + b.y;
        loc[i + 2] = a.z + b.z; loc[i + 3] = a.w + b.w;
    }
    float ss = 0.f;
#pragma unroll
    for (int i = 0; i < 8; i++) ss += loc[i] * loc[i];
    ss = blockReduceSum(ss);
    float r = rsqrtf(ss * (1.f / Dd) + EPSf);
    float o[8];
#pragma unroll
    for (int i = 0; i < 8; i++) o[i] = loc[i] * r * ln2w[c0 + i];
    *(float4*)&dst[c0]     = *(float4*)&o[0];
    *(float4*)&dst[c0 + 4] = *(float4*)&o[4];
}

__global__ void k_outscale(const float* __restrict__ hidden, float* __restrict__ out) {
    size_t total4 = (size_t)Bb * Ss * Dd / 4;
    for (size_t i = (size_t)blockIdx.x * blockDim.x + threadIdx.x; i < total4;
         i += (size_t)gridDim.x * blockDim.x) {
        size_t tok = (i * 4) >> 11;
        float sc = g_weights[tok];
        float4 h = ((const float4*)hidden)[i];
        h.x *= sc; h.y *= sc; h.z *= sc; h.w *= sc;
        ((float4*)out)[i] = h;
    }
}

__global__ void k_scatter(float* __restrict__ out) {
    int t = blockIdx.x;
    int b = t >> 10;
    int s = g_kidx[t];
    int tok = b * Ss + s;
    float sc = g_weights[tok];
    float*       o  = out     + (size_t)tok * Dd;
    const float* dl = g_delta + (size_t)t * Dd;
    const float* xk = g_X     + (size_t)t * Dd;
    for (int c = threadIdx.x * 4; c < Dd; c += blockDim.x * 4) {
        float4 d4 = *(const float4*)&dl[c];
        float4 x4 = *(const float4*)&xk[c];
        *(float4*)&o[c] = make_float4(d4.x * sc + x4.x, d4.y * sc + x4.y,
                                      d4.z * sc + x4.z, d4.w * sc + x4.w);
    }
}

// ----------------------------------------------------------------------------
// Launch
// ----------------------------------------------------------------------------
extern "C" void kernel_launch(void* const* d_in, const int* in_sizes, int n_in,
                              void* d_out, int out_size) {
    const float* hidden   = (const float*)d_in[0];
    const int*   pos_ids  = (const int*)d_in[1];
    const float* router_w = (const float*)d_in[4];
    const float* ln1w     = (const float*)d_in[5];
    const float* ln2w     = (const float*)d_in[6];
    const float* Wq       = (const float*)d_in[7];
    const float* Wk       = (const float*)d_in[8];
    const float* Wv       = (const float*)d_in[9];
    const float* Wo       = (const float*)d_in[10];
    const float* W1       = (const float*)d_in[11];
    const float* W2       = (const float*)d_in[12];
    float* out = (float*)d_out;

    cudaFuncSetAttribute(k_hg_main,   cudaFuncAttributeMaxDynamicSharedMemorySize, HG_SMEM);
    cudaFuncSetAttribute(k_hg_scores, cudaFuncAttributeMaxDynamicSharedMemorySize, HG_SMEM);
    cudaFuncSetAttribute(k_hg_av,     cudaFuncAttributeMaxDynamicSharedMemorySize, HG_SMEM);

#define SYM(p, g) cudaGetSymbolAddress((void**)&p, g)
    float *WqT, *WkT, *WvT, *WoT, *W1T, *W2T;
    float *h1, *q, *k, *v, *att, *ao, *h2n, *ffh, *dlt;
    SYM(WqT, g_WqT); SYM(WkT, g_WkT); SYM(WvT, g_WvT); SYM(WoT, g_WoT);
    SYM(W1T, g_W1T); SYM(W2T, g_W2T);
    SYM(h1, g_h1); SYM(q, g_q); SYM(k, g_k); SYM(v, g_v);
    SYM(att, g_att); SYM(ao, g_ao); SYM(h2n, g_h2n);
    SYM(ffh, g_ffh); SYM(dlt, g_delta);
#undef SYM

    dim3 tb(32, 8);
    k_transpose<<<dim3(Dd / 32, Dd / 32), tb>>>(Wq, WqT, Dd, Dd);
    k_transpose<<<dim3(Dd / 32, Dd / 32), tb>>>(Wk, WkT, Dd, Dd);
    k_transpose<<<dim3(Dd / 32, Dd / 32), tb>>>(Wv, WvT, Dd, Dd);
    k_transpose<<<dim3(Dd / 32, Dd / 32), tb>>>(Wo, WoT, Dd, Dd);
    k_transpose<<<dim3(FFd / 32, Dd / 32), tb>>>(W1, W1T, Dd, FFd);
    k_transpose<<<dim3(Dd / 32, FFd / 32), tb>>>(W2, W2T, FFd, Dd);

    k_router<<<(Bb * Ss) / 8, 256>>>(hidden, router_w);
    k_select<<<Bb, 1024>>>(pos_ids);
    k_gather_rms1<<<MTOT, 256>>>(hidden, ln1w);

    dim3 gD(Dd / 128, MTOT / 128);
    k_hg_main<<<gD, 256, HG_SMEM>>>(h1, WqT, q, nullptr, Dd, Dd, 0);
    k_hg_main<<<gD, 256, HG_SMEM>>>(h1, WkT, k, nullptr, Dd, Dd, 0);
    k_hg_main<<<gD, 256, HG_SMEM>>>(h1, WvT, v, nullptr, Dd, Dd, 0);

    k_rope<<<(MTOT * Hh * 32 + 255) / 256, 256>>>();
    k_vt<<<dim3(KK / 32, HD / 32, BH), tb>>>();
    k_hg_scores<<<dim3(KK / 128, KK / 128, BH), 256, HG_SMEM>>>();
    k_softmax<<<BH * KK, 128>>>();
    k_hg_av<<<dim3(1, KK / 128, BH), 256, HG_SMEM>>>();

    k_hg_main<<<gD, 256, HG_SMEM>>>(att, WoT, ao, nullptr, Dd, Dd, 0);
    k_h2rms<<<MTOT, 256>>>(ln2w);
    k_hg_main<<<dim3(FFd / 128, MTOT / 128), 256, HG_SMEM>>>(h2n, W1T, ffh, nullptr, Dd, FFd, 1);
    k_hg_main<<<gD, 256, HG_SMEM>>>(ffh, W2T, dlt, ao, FFd, Dd, 0);

    k_outscale<<<8192, 256>>>(hidden, out);
    k_scatter<<<MTOT, 256>>>(out);
}

// round 14
// speedup vs baseline: 1.5914x; 1.0216x over previous
#include <cuda_runtime.h>
#include <cuda_bf16.h>
#include <math.h>
#include <float.h>
#include <stdint.h>

#define Dd   2048
#define Hh   16
#define HD   128
#define HALF 64
#define FFd  8192
#define Bb   4
#define Ss   2048
#define KK   1024
#define MTOT (Bb * KK)
#define BH   (Bb * Hh)
#define QLD  (3 * Dd)          // row stride of fused qkv buffer
#define EPSf 1e-6f
#define SM_SCALE 0.08838834764831843f

// ----------------------------------------------------------------------------
// Scratch (device globals)
// ----------------------------------------------------------------------------
__device__ float g_weights[Bb * Ss];
__device__ int   g_kidx[MTOT];
__device__ int   g_kpos[MTOT];
__device__ int   g_inv [Bb * Ss];                     // token -> kept slot | -1
__device__ float g_X   [(size_t)MTOT * Dd];
__device__ float g_h1  [(size_t)MTOT * Dd];
__device__ float g_qkv [(size_t)MTOT * QLD];          // [tok][q|k|v]
__device__ float g_vT  [(size_t)BH * HD * KK];        // per-head V^T [d][tok]
__device__ float g_scores[(size_t)BH * KK * KK];
__device__ float g_att [(size_t)MTOT * Dd];
__device__ float g_ao  [(size_t)MTOT * Dd];
__device__ float g_h2n [(size_t)MTOT * Dd];
__device__ float g_ffh [(size_t)MTOT * FFd];
__device__ float g_delta[(size_t)MTOT * Dd];
// transposed weights [N, K] fp32
__device__ float g_WqkvT[(size_t)QLD * Dd];           // rows: Wq | Wk | Wv
__device__ float g_WoT[(size_t)Dd * Dd];
__device__ float g_W1T[(size_t)FFd * Dd];
__device__ float g_W2T[(size_t)Dd * FFd];

// ----------------------------------------------------------------------------
// Helpers
// ----------------------------------------------------------------------------
__device__ __forceinline__ float warpReduceSum(float v) {
#pragma unroll
    for (int o = 16; o > 0; o >>= 1) v += __shfl_xor_sync(0xffffffffu, v, o);
    return v;
}
__device__ __forceinline__ float warpReduceMax(float v) {
#pragma unroll
    for (int o = 16; o > 0; o >>= 1) v = fmaxf(v, __shfl_xor_sync(0xffffffffu, v, o));
    return v;
}
__device__ float blockReduceSum(float v) {
    __shared__ float sm[8];
    __shared__ float res;
    int lane = threadIdx.x & 31, w = threadIdx.x >> 5;
    int nw = (blockDim.x + 31) >> 5;
    v = warpReduceSum(v);
    if (lane == 0) sm[w] = v;
    __syncthreads();
    if (w == 0) {
        float x = (lane < nw) ? sm[lane] : 0.f;
        x = warpReduceSum(x);
        if (lane == 0) res = x;
    }
    __syncthreads();
    return res;
}
__device__ float blockReduceMax(float v) {
    __shared__ float sm[8];
    __shared__ float res;
    int lane = threadIdx.x & 31, w = threadIdx.x >> 5;
    int nw = (blockDim.x + 31) >> 5;
    v = warpReduceMax(v);
    if (lane == 0) sm[w] = v;
    __syncthreads();
    if (w == 0) {
        float x = (lane < nw) ? sm[lane] : -FLT_MAX;
        x = warpReduceMax(x);
        if (lane == 0) res = x;
    }
    __syncthreads();
    return res;
}
__device__ __forceinline__ float gelu_tanh(float x) {
    float x3 = x * x * x;
    float t = tanhf(0.7978845608028654f * (x + 0.044715f * x3));
    return 0.5f * x * (1.f + t);
}
__device__ __forceinline__ uint32_t smem_u32(const void* p) {
    uint32_t a;
    asm("{ .reg .u64 t; cvta.to.shared.u64 t, %1; cvt.u32.u64 %0, t; }" : "=r"(a) : "l"(p));
    return a;
}
// fp32 pair -> bf16x2 hi + bf16x2 lo
__device__ __forceinline__ void cvt_hilo(float a, float b, uint32_t& h, uint32_t& l) {
    __nv_bfloat162 hv = __floats2bfloat162_rn(a, b);
    h = *reinterpret_cast<uint32_t*>(&hv);
    float fa = __uint_as_float(h << 16);
    float fb = __uint_as_float(h & 0xffff0000u);
    __nv_bfloat162 lv = __floats2bfloat162_rn(a - fa, b - fb);
    l = *reinterpret_cast<uint32_t*>(&lv);
}

// ----------------------------------------------------------------------------
// HMMA primitives (base PTX, works on plain sm_103 target)
// ----------------------------------------------------------------------------
__device__ __forceinline__ void ldsm4(uint32_t* r, uint32_t a) {
    asm volatile("ldmatrix.sync.aligned.m8n8.x4.shared.b16 {%0,%1,%2,%3}, [%4];"
        : "=r"(r[0]), "=r"(r[1]), "=r"(r[2]), "=r"(r[3]) : "r"(a));
}
__device__ __forceinline__ void ldsm2(uint32_t* r, uint32_t a) {
    asm volatile("ldmatrix.sync.aligned.m8n8.x2.shared.b16 {%0,%1}, [%2];"
        : "=r"(r[0]), "=r"(r[1]) : "r"(a));
}
__device__ __forceinline__ void mma16816(float* c, const uint32_t* a, const uint32_t* b) {
    asm volatile("mma.sync.aligned.m16n8k16.row.col.f32.bf16.bf16.f32 "
        "{%0,%1,%2,%3}, {%4,%5,%6,%7}, {%8,%9}, {%0,%1,%2,%3};"
        : "+f"(c[0]), "+f"(c[1]), "+f"(c[2]), "+f"(c[3])
        : "r"(a[0]), "r"(a[1]), "r"(a[2]), "r"(a[3]), "r"(b[0]), "r"(b[1]));
}

// SMEM layout per stage: Ahi[128][40] Alo Bhi Blo bf16, row stride 80B
#define ROWB   80
#define TILE_B 10240
#define STAGE_B 40960
#define HG_SMEM (2 * STAGE_B)

// ----------------------------------------------------------------------------
// HMMA split-bf16 GEMM body: C[128,128 tile] = A[M,K] @ Bt[N,K]^T (+Add, act)
// 256 threads = 8 warps (2x4), warp tile 64x32, BK=32, double buffer.
// (Proven R6 schedule — do not restructure.)
// ----------------------------------------------------------------------------
__device__ __forceinline__ void hgemm_body(
    const float* __restrict__ A, int lda,
    const float* __restrict__ Bt, int ldb,
    float* __restrict__ C, int ldc,
    const float* __restrict__ Add,
    int Kd, int act)
{
    extern __shared__ char smc[];
    const uint32_t sbase = smem_u32(smc);
    const int tid  = threadIdx.x;
    const int m0   = blockIdx.y * 128, n0 = blockIdx.x * 128;
    const int wid  = tid >> 5, lane = tid & 31;
    const int wm   = (wid >> 2) * 64;
    const int wn   = (wid & 3) * 32;
    const int lrow = tid >> 1;
    const int lf4  = (tid & 1) * 4;

    const float4* gA = (const float4*)(A  + (size_t)(m0 + lrow) * lda);
    const float4* gB = (const float4*)(Bt + (size_t)(n0 + lrow) * ldb);

    float acc[4][4][4];
#pragma unroll
    for (int i = 0; i < 4; i++)
#pragma unroll
        for (int j = 0; j < 4; j++)
#pragma unroll
            for (int r = 0; r < 4; r++) acc[i][j][r] = 0.f;

    const int a_row = (lane & 7) + ((lane >> 3) & 1) * 8;
    const int a_cb  = (lane >> 4) * 16;
    const int ll    = lane & 15;
    const int b_row = ll & 7;
    const int b_cb  = (ll >> 3) * 16;

    float4 ra[4], rb[4];
    const int nch = Kd >> 5;

    // prefetch + store chunk 0
#pragma unroll
    for (int i = 0; i < 4; i++) { ra[i] = gA[lf4 + i]; rb[i] = gB[lf4 + i]; }
    {
        char* st = smc;
#pragma unroll
        for (int i = 0; i < 4; i++) {
            int f4 = lf4 + i;
            uint32_t h01, h23, l01, l23;
            cvt_hilo(ra[i].x, ra[i].y, h01, l01);
            cvt_hilo(ra[i].z, ra[i].w, h23, l23);
            int off = lrow * ROWB + f4 * 8;
            *(uint2*)(st + off)          = make_uint2(h01, h23);
            *(uint2*)(st + TILE_B + off) = make_uint2(l01, l23);
            cvt_hilo(rb[i].x, rb[i].y, h01, l01);
            cvt_hilo(rb[i].z, rb[i].w, h23, l23);
            *(uint2*)(st + 2 * TILE_B + off) = make_uint2(h01, h23);
            *(uint2*)(st + 3 * TILE_B + off) = make_uint2(l01, l23);
        }
    }
    __syncthreads();

    for (int c = 0; c < nch; c++) {
        const int s = c & 1;
        if (c + 1 < nch) {
            int fb = ((c + 1) << 3) + lf4;
#pragma unroll
            for (int i = 0; i < 4; i++) { ra[i] = gA[fb + i]; rb[i] = gB[fb + i]; }
        }
        // compute from stage s
        const uint32_t sb = sbase + s * STAGE_B;
#pragma unroll
        for (int ks = 0; ks < 2; ks++) {
            const int kb = ks * 32;
            uint32_t ahi[4][4], alo[4][4];
#pragma unroll
            for (int mf = 0; mf < 4; mf++) {
                uint32_t ad = sb + (wm + mf * 16 + a_row) * ROWB + kb + a_cb;
                ldsm4(ahi[mf], ad);
                ldsm4(alo[mf], ad + TILE_B);
            }
            uint32_t bhi[4][2], blo[4][2];
#pragma unroll
            for (int nf = 0; nf < 4; nf++) {
                uint32_t bd = sb + 2 * TILE_B + (wn + nf * 8 + b_row) * ROWB + kb + b_cb;
                ldsm2(bhi[nf], bd);
                ldsm2(blo[nf], bd + TILE_B);
            }
#pragma unroll
            for (int mf = 0; mf < 4; mf++)
#pragma unroll
                for (int nf = 0; nf < 4; nf++) {
                    mma16816(acc[mf][nf], ahi[mf], bhi[nf]);
                    mma16816(acc[mf][nf], ahi[mf], blo[nf]);
                    mma16816(acc[mf][nf], alo[mf], bhi[nf]);
                }
        }
        __syncthreads();
        if (c + 1 < nch) {
            char* st = smc + (s ^ 1) * STAGE_B;
#pragma unroll
            for (int i = 0; i < 4; i++) {
                int f4 = lf4 + i;
                uint32_t h01, h23, l01, l23;
                cvt_hilo(ra[i].x, ra[i].y, h01, l01);
                cvt_hilo(ra[i].z, ra[i].w, h23, l23);
                int off = lrow * ROWB + f4 * 8;
                *(uint2*)(st + off)          = make_uint2(h01, h23);
                *(uint2*)(st + TILE_B + off) = make_uint2(l01, l23);
                cvt_hilo(rb[i].x, rb[i].y, h01, l01);
                cvt_hilo(rb[i].z, rb[i].w, h23, l23);
                *(uint2*)(st + 2 * TILE_B + off) = make_uint2(h01, h23);
                *(uint2*)(st + 3 * TILE_B + off) = make_uint2(l01, l23);
            }
            __syncthreads();
        }
    }

    // epilogue
#pragma unroll
    for (int mf = 0; mf < 4; mf++) {
        int rbase = m0 + wm + mf * 16 + (lane >> 2);
#pragma unroll
        for (int nf = 0; nf < 4; nf++) {
            int cb = n0 + wn + nf * 8 + (lane & 3) * 2;
#pragma unroll
            for (int hlf = 0; hlf < 2; hlf++) {
                int row = rbase + hlf * 8;
                float vx = acc[mf][nf][hlf * 2];
                float vy = acc[mf][nf][hlf * 2 + 1];
                if (Add) {
                    const float* ap = Add + (size_t)row * ldc + cb;
                    vx += ap[0]; vy += ap[1];
                }
                if (act == 1) { vx = gelu_tanh(vx); vy = gelu_tanh(vy); }
                float2* cp = (float2*)(C + (size_t)row * ldc + cb);
                *cp = make_float2(vx, vy);
            }
        }
    }
}

// Wrappers
__global__ void __launch_bounds__(256) k_hg_main(
    const float* __restrict__ A, const float* __restrict__ Bt,
    float* __restrict__ C, const float* __restrict__ Add,
    int Kd, int ldc, int act)
{
    hgemm_body(A, Kd, Bt, Kd, C, ldc, Add, Kd, act);
}

__global__ void __launch_bounds__(256) k_hg_scores() {
    if (blockIdx.x * 128 > blockIdx.y * 128 + 127) return;  // fully masked tile
    int z = blockIdx.z;
    int b = z >> 4, h = z & 15;
    const float* A  = g_qkv + (size_t)b * KK * QLD + (size_t)h * HD;       // Q
    const float* Bt = g_qkv + (size_t)b * KK * QLD + (size_t)h * HD + Dd;  // K
    float* C = g_scores + (size_t)z * KK * KK;
    hgemm_body(A, QLD, Bt, QLD, C, KK, nullptr, HD, 0);
}

__global__ void __launch_bounds__(256) k_hg_av() {
    int z = blockIdx.z;
    int b = z >> 4, h = z & 15;
    const float* A  = g_scores + (size_t)z * KK * KK;
    const float* Bt = g_vT + (size_t)z * HD * KK;
    float* C = g_att + (size_t)b * KK * Dd + (size_t)h * HD;
    int Keff = (blockIdx.y + 1) * 128;   // causal: probs are exactly 0 beyond
    hgemm_body(A, KK, Bt, KK, C, Dd, nullptr, Keff, 0);
}

// ----------------------------------------------------------------------------
// Transposes
// ----------------------------------------------------------------------------
__global__ void k_transpose(const float* __restrict__ W, float* __restrict__ WT,
                            int Kd, int Nd) {
    __shared__ float t[32][33];
    int k0 = blockIdx.y * 32, n0 = blockIdx.x * 32;
    int x = threadIdx.x, y = threadIdx.y;
#pragma unroll
    for (int i = 0; i < 32; i += 8)
        t[y + i][x] = W[(size_t)(k0 + y + i) * Nd + n0 + x];
    __syncthreads();
#pragma unroll
    for (int i = 0; i < 32; i += 8)
        WT[(size_t)(n0 + y + i) * Kd + k0 + x] = t[x][y + i];
}

__global__ void k_vt() {   // g_qkv V slice [b][tok][h][d] -> g_vT [b*H+h][d][tok]
    __shared__ float t[32][33];
    int z = blockIdx.z, b = z >> 4, h = z & 15;
    int tok0 = blockIdx.x * 32, d0 = blockIdx.y * 32;
    int x = threadIdx.x, y = threadIdx.y;
#pragma unroll
    for (int i = 0; i < 32; i += 8)
        t[y + i][x] = g_qkv[(size_t)(b * KK + tok0 + y + i) * QLD + 2 * Dd + h * HD + d0 + x];
    __syncthreads();
#pragma unroll
    for (int i = 0; i < 32; i += 8)
        g_vT[(size_t)z * HD * KK + (size_t)(d0 + y + i) * KK + tok0 + x] = t[x][y + i];
}

// ----------------------------------------------------------------------------
// Router / select / gather
// ----------------------------------------------------------------------------
__global__ void k_router(const float* __restrict__ hidden, const float* __restrict__ rw) {
    int wid  = (blockIdx.x * blockDim.x + threadIdx.x) >> 5;
    int lane = threadIdx.x & 31;
    if (wid >= Bb * Ss) return;
    const float4* x  = (const float4*)(hidden + (size_t)wid * Dd);
    const float4* r4 = (const float4*)rw;
    float s = 0.f;
#pragma unroll 4
    for (int i = lane; i < Dd / 4; i += 32) {
        float4 a = x[i], b = r4[i];
        s += a.x * b.x + a.y * b.y + a.z * b.z + a.w * b.w;
    }
    s = warpReduceSum(s);
    if (lane == 0) g_weights[wid] = 1.f / (1.f + expf(-s));
}

__global__ void k_select(const int* __restrict__ pos_ids) {
    __shared__ float w[Ss];
    __shared__ unsigned char sel[Ss];
    int b = blockIdx.x;
    for (int s = threadIdx.x; s < Ss; s += blockDim.x) w[s] = g_weights[b * Ss + s];
    __syncthreads();
    for (int s = threadIdx.x; s < Ss; s += blockDim.x) {
        float ws = w[s];
        int r = 0;
        for (int t = 0; t < Ss; t++) {
            float wt = w[t];
            r += (wt > ws) || (wt == ws && t < s);
        }
        sel[s] = (r < KK) ? 1 : 0;
    }
    __syncthreads();
    for (int s = threadIdx.x; s < Ss; s += blockDim.x) {
        if (sel[s]) {
            int j = 0;
            for (int t = 0; t < s; t++) j += sel[t];
            g_kidx[b * KK + j] = s;
            g_kpos[b * KK + j] = pos_ids[s];
            g_inv [b * Ss + s] = j;
        } else {
            g_inv [b * Ss + s] = -1;
        }
    }
}

// 256 threads/token; thread owns 8 consecutive columns -> vector accesses
__global__ void k_gather_rms1(const float* __restrict__ hidden, const float* __restrict__ ln1w) {
    int t = blockIdx.x;
    int b = t >> 10;
    int s = g_kidx[t];
    const float* src = hidden + ((size_t)(b * Ss + s)) * Dd;
    float* xdst = g_X  + (size_t)t * Dd;
    float* hdst = g_h1 + (size_t)t * Dd;
    int c0 = threadIdx.x * 8;
    float loc[8];
    *(float4*)&loc[0] = *(const float4*)&src[c0];
    *(float4*)&loc[4] = *(const float4*)&src[c0 + 4];
    float ss = 0.f;
#pragma unroll
    for (int i = 0; i < 8; i++) ss += loc[i] * loc[i];
    ss = blockReduceSum(ss);
    float r = rsqrtf(ss * (1.f / Dd) + EPSf);
    *(float4*)&xdst[c0]     = *(float4*)&loc[0];
    *(float4*)&xdst[c0 + 4] = *(float4*)&loc[4];
    float o[8];
#pragma unroll
    for (int i = 0; i < 8; i++) o[i] = loc[i] * r * ln1w[c0 + i];
    *(float4*)&hdst[c0]     = *(float4*)&o[0];
    *(float4*)&hdst[c0 + 4] = *(float4*)&o[4];
}

// ----------------------------------------------------------------------------
// RoPE on fused qkv buffer (fp32 in-place, float2 vectorized)
// ----------------------------------------------------------------------------
__global__ void k_rope() {
    int t = blockIdx.x * blockDim.x + threadIdx.x;   // MTOT * H * 32
    if (t >= MTOT * Hh * 32) return;
    int dp  = (t & 31) * 2;
    int th  = t >> 5;
    int h   = th & 15;
    int tok = th >> 4;
    int pos = g_kpos[tok];
    float fp = (float)pos;
    float f0 = expf((float)dp       * (-9.210340371976184f / 64.f));
    float f1 = expf((float)(dp + 1) * (-9.210340371976184f / 64.f));
    float c0 = cosf(fp * f0), s0 = sinf(fp * f0);
    float c1 = cosf(fp * f1), s1 = sinf(fp * f1);
    size_t qb = (size_t)tok * QLD + h * HD + dp;     // Q slice
    size_t kb = qb + Dd;                              // K slice
    float2 q1 = *(float2*)&g_qkv[qb];
    float2 q2 = *(float2*)&g_qkv[qb + HALF];
    *(float2*)&g_qkv[qb]        = make_float2(q1.x * c0 - q2.x * s0, q1.y * c1 - q2.y * s1);
    *(float2*)&g_qkv[qb + HALF] = make_float2(q2.x * c0 + q1.x * s0, q2.y * c1 + q1.y * s1);
    float2 k1 = *(float2*)&g_qkv[kb];
    float2 k2 = *(float2*)&g_qkv[kb + HALF];
    *(float2*)&g_qkv[kb]        = make_float2(k1.x * c0 - k2.x * s0, k1.y * c1 - k2.y * s1);
    *(float2*)&g_qkv[kb + HALF] = make_float2(k2.x * c0 + k1.x * s0, k2.y * c1 + k1.y * s1);
}

// ----------------------------------------------------------------------------
// Softmax: 128 threads/row, thread owns 8 cols; only covering tiles touched
// ----------------------------------------------------------------------------
__global__ void k_softmax() {
    int row = blockIdx.x;
    int q = row & (KK - 1);
    float* r = g_scores + (size_t)row * KK;
    int n = q + 1;
    int ncov = ((q >> 7) + 1) << 7;          // AV reads exactly [0, ncov)
    int c0 = threadIdx.x * 8;
    bool active = (c0 < ncov);
    float v[8];
    if (active) {
        *(float4*)&v[0] = *(const float4*)&r[c0];
        *(float4*)&v[4] = *(const float4*)&r[c0 + 4];
    }
    float m = -FLT_MAX;
    if (active) {
#pragma unroll
        for (int i = 0; i < 8; i++)
            if (c0 + i < n) m = fmaxf(m, v[i]);
    }
    m = blockReduceMax(m);
    float e[8];
    float sum = 0.f;
    if (active) {
#pragma unroll
        for (int i = 0; i < 8; i++) {
            e[i] = (c0 + i < n) ? expf(SM_SCALE * (v[i] - m)) : 0.f;
            sum += e[i];
        }
    }
    sum = blockReduceSum(sum);
    if (active) {
        float inv = 1.f / sum;
#pragma unroll
        for (int i = 0; i < 8; i++) e[i] *= inv;
        *(float4*)&r[c0]     = *(float4*)&e[0];
        *(float4*)&r[c0 + 4] = *(float4*)&e[4];
    }
}

// ----------------------------------------------------------------------------
// h2 = X + ao ; rmsnorm -> fp32 (vectorized)
// ----------------------------------------------------------------------------
__global__ void k_h2rms(const float* __restrict__ ln2w) {
    int t = blockIdx.x;
    const float* xa = g_X  + (size_t)t * Dd;
    const float* ao = g_ao + (size_t)t * Dd;
    float* dst = g_h2n + (size_t)t * Dd;
    int c0 = threadIdx.x * 8;
    float loc[8];
#pragma unroll
    for (int i = 0; i < 8; i += 4) {
        float4 a = *(const float4*)&xa[c0 + i];
        float4 b = *(const float4*)&ao[c0 + i];
        loc[i] = a.x + b.x; loc[i + 1] = a.y + b.y;
        loc[i + 2] = a.z + b.z; loc[i + 3] = a.w + b.w;
    }
    float ss = 0.f;
#pragma unroll
    for (int i = 0; i < 8; i++) ss += loc[i] * loc[i];
    ss = blockReduceSum(ss);
    float r = rsqrtf(ss * (1.f / Dd) + EPSf);
    float o[8];
#pragma unroll
    for (int i = 0; i < 8; i++) o[i] = loc[i] * r * ln2w[c0 + i];
    *(float4*)&dst[c0]     = *(float4*)&o[0];
    *(float4*)&dst[c0 + 4] = *(float4*)&o[4];
}

// ----------------------------------------------------------------------------
// Final output: kept rows = delta*w + kept ; others = hidden*w (single pass)
// ----------------------------------------------------------------------------
__global__ void k_final(const float* __restrict__ hidden, float* __restrict__ out) {
    int row = blockIdx.x;                 // 0 .. Bb*Ss-1
    int b   = row >> 11;                  // / Ss
    int inv = g_inv[row];
    float w = g_weights[row];
    float* o = out + (size_t)row * Dd;
    int c0 = threadIdx.x * 8;
    if (inv >= 0) {
        size_t t = ((size_t)(b * KK + inv)) * Dd;
        const float* dl = g_delta + t;
        const float* xk = g_X + t;
#pragma unroll
        for (int i = 0; i < 8; i += 4) {
            float4 d4 = *(const float4*)&dl[c0 + i];
            float4 x4 = *(const float4*)&xk[c0 + i];
            *(float4*)&o[c0 + i] = make_float4(d4.x * w + x4.x, d4.y * w + x4.y,
                                               d4.z * w + x4.z, d4.w * w + x4.w);
        }
    } else {
        const float* h = hidden + (size_t)row * Dd;
#pragma unroll
        for (int i = 0; i < 8; i += 4) {
            float4 h4 = *(const float4*)&h[c0 + i];
            *(float4*)&o[c0 + i] = make_float4(h4.x * w, h4.y * w, h4.z * w, h4.w * w);
        }
    }
}

// ----------------------------------------------------------------------------
// Launch
// ----------------------------------------------------------------------------
extern "C" void kernel_launch(void* const* d_in, const int* in_sizes, int n_in,
                              void* d_out, int out_size) {
    const float* hidden   = (const float*)d_in[0];
    const int*   pos_ids  = (const int*)d_in[1];
    const float* router_w = (const float*)d_in[4];
    const float* ln1w     = (const float*)d_in[5];
    const float* ln2w     = (const float*)d_in[6];
    const float* Wq       = (const float*)d_in[7];
    const float* Wk       = (const float*)d_in[8];
    const float* Wv       = (const float*)d_in[9];
    const float* Wo       = (const float*)d_in[10];
    const float* W1       = (const float*)d_in[11];
    const float* W2       = (const float*)d_in[12];
    float* out = (float*)d_out;

    cudaFuncSetAttribute(k_hg_main,   cudaFuncAttributeMaxDynamicSharedMemorySize, HG_SMEM);
    cudaFuncSetAttribute(k_hg_scores, cudaFuncAttributeMaxDynamicSharedMemorySize, HG_SMEM);
    cudaFuncSetAttribute(k_hg_av,     cudaFuncAttributeMaxDynamicSharedMemorySize, HG_SMEM);

#define SYM(p, g) cudaGetSymbolAddress((void**)&p, g)
    float *WqkvT, *WoT, *W1T, *W2T;
    float *h1, *qkv, *att, *ao, *h2n, *ffh, *dlt;
    SYM(WqkvT, g_WqkvT); SYM(WoT, g_WoT);
    SYM(W1T, g_W1T); SYM(W2T, g_W2T);
    SYM(h1, g_h1); SYM(qkv, g_qkv);
    SYM(att, g_att); SYM(ao, g_ao); SYM(h2n, g_h2n);
    SYM(ffh, g_ffh); SYM(dlt, g_delta);
#undef SYM

    dim3 tb(32, 8);
    const size_t DD = (size_t)Dd * Dd;
    k_transpose<<<dim3(Dd / 32, Dd / 32), tb>>>(Wq, WqkvT,          Dd, Dd);
    k_transpose<<<dim3(Dd / 32, Dd / 32), tb>>>(Wk, WqkvT + DD,     Dd, Dd);
    k_transpose<<<dim3(Dd / 32, Dd / 32), tb>>>(Wv, WqkvT + 2 * DD, Dd, Dd);
    k_transpose<<<dim3(Dd / 32, Dd / 32), tb>>>(Wo, WoT, Dd, Dd);
    k_transpose<<<dim3(FFd / 32, Dd / 32), tb>>>(W1, W1T, Dd, FFd);
    k_transpose<<<dim3(Dd / 32, FFd / 32), tb>>>(W2, W2T, FFd, Dd);

    k_router<<<(Bb * Ss) / 8, 256>>>(hidden, router_w);
    k_select<<<Bb, 1024>>>(pos_ids);
    k_gather_rms1<<<MTOT, 256>>>(hidden, ln1w);

    // fused QKV: C is [MTOT][3*Dd], B rows 0..6143 = Wq|Wk|Wv transposed
    k_hg_main<<<dim3(QLD / 128, MTOT / 128), 256, HG_SMEM>>>(
        h1, WqkvT, qkv, nullptr, Dd, QLD, 0);

    k_rope<<<(MTOT * Hh * 32 + 255) / 256, 256>>>();
    k_vt<<<dim3(KK / 32, HD / 32, BH), tb>>>();
    k_hg_scores<<<dim3(KK / 128, KK / 128, BH), 256, HG_SMEM>>>();
    k_softmax<<<BH * KK, 128>>>();
    k_hg_av<<<dim3(1, KK / 128, BH), 256, HG_SMEM>>>();

    dim3 gD(Dd / 128, MTOT / 128);
    k_hg_main<<<gD, 256, HG_SMEM>>>(att, WoT, ao, nullptr, Dd, Dd, 0);
    k_h2rms<<<MTOT, 256>>>(ln2w);
    k_hg_main<<<dim3(FFd / 128, MTOT / 128), 256, HG_SMEM>>>(h2n, W1T, ffh, nullptr, Dd, FFd, 1);
    k_hg_main<<<gD, 256, HG_SMEM>>>(ffh, W2T, dlt, ao, FFd, Dd, 0);

    k_final<<<Bb * Ss, 256>>>(hidden, out);
}

// round 15
// speedup vs baseline: 1.6117x; 1.0127x over previous
#include <cuda_runtime.h>
#include <cuda_bf16.h>
#include <math.h>
#include <float.h>
#include <stdint.h>

#define Dd   2048
#define Hh   16
#define HD   128
#define HALF 64
#define FFd  8192
#define Bb   4
#define Ss   2048
#define KK   1024
#define MTOT (Bb * KK)
#define BH   (Bb * Hh)
#define QLD  (3 * Dd)          // row stride of fused qkv buffer
#define EPSf 1e-6f
#define SM_SCALE 0.08838834764831843f

// ----------------------------------------------------------------------------
// Scratch (device globals)
// ----------------------------------------------------------------------------
__device__ float g_weights[Bb * Ss];
__device__ int   g_kidx[MTOT];
__device__ int   g_kpos[MTOT];
__device__ int   g_inv [Bb * Ss];                     // token -> kept slot | -1
__device__ float g_X   [(size_t)MTOT * Dd];
__device__ float g_h1  [(size_t)MTOT * Dd];
__device__ float g_qkv [(size_t)MTOT * QLD];          // [tok][q|k|v]
__device__ float g_vT  [(size_t)BH * HD * KK];        // per-head V^T [d][tok]
__device__ float g_scores[(size_t)BH * KK * KK];
__device__ float g_att [(size_t)MTOT * Dd];
__device__ float g_ao  [(size_t)MTOT * Dd];
__device__ float g_h2n [(size_t)MTOT * Dd];
__device__ float g_ffh [(size_t)MTOT * FFd];
__device__ float g_delta[(size_t)MTOT * Dd];
// transposed weights [N, K] fp32
__device__ float g_WqkvT[(size_t)QLD * Dd];           // rows: Wq | Wk | Wv
__device__ float g_WoT[(size_t)Dd * Dd];
__device__ float g_W1T[(size_t)FFd * Dd];
__device__ float g_W2T[(size_t)Dd * FFd];

// ----------------------------------------------------------------------------
// Helpers
// ----------------------------------------------------------------------------
__device__ __forceinline__ float warpReduceSum(float v) {
#pragma unroll
    for (int o = 16; o > 0; o >>= 1) v += __shfl_xor_sync(0xffffffffu, v, o);
    return v;
}
__device__ __forceinline__ float warpReduceMax(float v) {
#pragma unroll
    for (int o = 16; o > 0; o >>= 1) v = fmaxf(v, __shfl_xor_sync(0xffffffffu, v, o));
    return v;
}
__device__ float blockReduceSum(float v) {
    __shared__ float sm[8];
    __shared__ float res;
    int lane = threadIdx.x & 31, w = threadIdx.x >> 5;
    int nw = (blockDim.x + 31) >> 5;
    v = warpReduceSum(v);
    if (lane == 0) sm[w] = v;
    __syncthreads();
    if (w == 0) {
        float x = (lane < nw) ? sm[lane] : 0.f;
        x = warpReduceSum(x);
        if (lane == 0) res = x;
    }
    __syncthreads();
    return res;
}
__device__ float blockReduceMax(float v) {
    __shared__ float sm[8];
    __shared__ float res;
    int lane = threadIdx.x & 31, w = threadIdx.x >> 5;
    int nw = (blockDim.x + 31) >> 5;
    v = warpReduceMax(v);
    if (lane == 0) sm[w] = v;
    __syncthreads();
    if (w == 0) {
        float x = (lane < nw) ? sm[lane] : -FLT_MAX;
        x = warpReduceMax(x);
        if (lane == 0) res = x;
    }
    __syncthreads();
    return res;
}
__device__ __forceinline__ float gelu_tanh(float x) {
    float x3 = x * x * x;
    float t = tanhf(0.7978845608028654f * (x + 0.044715f * x3));
    return 0.5f * x * (1.f + t);
}
__device__ __forceinline__ uint32_t smem_u32(const void* p) {
    uint32_t a;
    asm("{ .reg .u64 t; cvta.to.shared.u64 t, %1; cvt.u32.u64 %0, t; }" : "=r"(a) : "l"(p));
    return a;
}
// fp32 pair -> bf16x2 hi + bf16x2 lo
__device__ __forceinline__ void cvt_hilo(float a, float b, uint32_t& h, uint32_t& l) {
    __nv_bfloat162 hv = __floats2bfloat162_rn(a, b);
    h = *reinterpret_cast<uint32_t*>(&hv);
    float fa = __uint_as_float(h << 16);
    float fb = __uint_as_float(h & 0xffff0000u);
    __nv_bfloat162 lv = __floats2bfloat162_rn(a - fa, b - fb);
    l = *reinterpret_cast<uint32_t*>(&lv);
}

// ----------------------------------------------------------------------------
// HMMA primitives (base PTX, works on plain sm_103 target)
// ----------------------------------------------------------------------------
__device__ __forceinline__ void ldsm4(uint32_t* r, uint32_t a) {
    asm volatile("ldmatrix.sync.aligned.m8n8.x4.shared.b16 {%0,%1,%2,%3}, [%4];"
        : "=r"(r[0]), "=r"(r[1]), "=r"(r[2]), "=r"(r[3]) : "r"(a));
}
__device__ __forceinline__ void ldsm2(uint32_t* r, uint32_t a) {
    asm volatile("ldmatrix.sync.aligned.m8n8.x2.shared.b16 {%0,%1}, [%2];"
        : "=r"(r[0]), "=r"(r[1]) : "r"(a));
}
__device__ __forceinline__ void mma16816(float* c, const uint32_t* a, const uint32_t* b) {
    asm volatile("mma.sync.aligned.m16n8k16.row.col.f32.bf16.bf16.f32 "
        "{%0,%1,%2,%3}, {%4,%5,%6,%7}, {%8,%9}, {%0,%1,%2,%3};"
        : "+f"(c[0]), "+f"(c[1]), "+f"(c[2]), "+f"(c[3])
        : "r"(a[0]), "r"(a[1]), "r"(a[2]), "r"(a[3]), "r"(b[0]), "r"(b[1]));
}

// SMEM layout per stage: Ahi[128][40] Alo Bhi Blo bf16, row stride 80B
#define ROWB   80
#define TILE_B 10240
#define STAGE_B 40960
#define HG_SMEM (2 * STAGE_B)

// ----------------------------------------------------------------------------
// HMMA split-bf16 GEMM body: C[128,128 tile] = A[M,K] @ Bt[N,K]^T (+Add, act)
// 256 threads = 8 warps (2x4), warp tile 64x32, BK=32, double buffer.
// (Proven R6 schedule — do not restructure.)
// ----------------------------------------------------------------------------
__device__ __forceinline__ void hgemm_body(
    const float* __restrict__ A, int lda,
    const float* __restrict__ Bt, int ldb,
    float* __restrict__ C, int ldc,
    const float* __restrict__ Add,
    int Kd, int act)
{
    extern __shared__ char smc[];
    const uint32_t sbase = smem_u32(smc);
    const int tid  = threadIdx.x;
    const int m0   = blockIdx.y * 128, n0 = blockIdx.x * 128;
    const int wid  = tid >> 5, lane = tid & 31;
    const int wm   = (wid >> 2) * 64;
    const int wn   = (wid & 3) * 32;
    const int lrow = tid >> 1;
    const int lf4  = (tid & 1) * 4;

    const float4* gA = (const float4*)(A  + (size_t)(m0 + lrow) * lda);
    const float4* gB = (const float4*)(Bt + (size_t)(n0 + lrow) * ldb);

    float acc[4][4][4];
#pragma unroll
    for (int i = 0; i < 4; i++)
#pragma unroll
        for (int j = 0; j < 4; j++)
#pragma unroll
            for (int r = 0; r < 4; r++) acc[i][j][r] = 0.f;

    const int a_row = (lane & 7) + ((lane >> 3) & 1) * 8;
    const int a_cb  = (lane >> 4) * 16;
    const int ll    = lane & 15;
    const int b_row = ll & 7;
    const int b_cb  = (ll >> 3) * 16;

    float4 ra[4], rb[4];
    const int nch = Kd >> 5;

    // prefetch + store chunk 0
#pragma unroll
    for (int i = 0; i < 4; i++) { ra[i] = gA[lf4 + i]; rb[i] = gB[lf4 + i]; }
    {
        char* st = smc;
#pragma unroll
        for (int i = 0; i < 4; i++) {
            int f4 = lf4 + i;
            uint32_t h01, h23, l01, l23;
            cvt_hilo(ra[i].x, ra[i].y, h01, l01);
            cvt_hilo(ra[i].z, ra[i].w, h23, l23);
            int off = lrow * ROWB + f4 * 8;
            *(uint2*)(st + off)          = make_uint2(h01, h23);
            *(uint2*)(st + TILE_B + off) = make_uint2(l01, l23);
            cvt_hilo(rb[i].x, rb[i].y, h01, l01);
            cvt_hilo(rb[i].z, rb[i].w, h23, l23);
            *(uint2*)(st + 2 * TILE_B + off) = make_uint2(h01, h23);
            *(uint2*)(st + 3 * TILE_B + off) = make_uint2(l01, l23);
        }
    }
    __syncthreads();

    for (int c = 0; c < nch; c++) {
        const int s = c & 1;
        if (c + 1 < nch) {
            int fb = ((c + 1) << 3) + lf4;
#pragma unroll
            for (int i = 0; i < 4; i++) { ra[i] = gA[fb + i]; rb[i] = gB[fb + i]; }
        }
        // compute from stage s
        const uint32_t sb = sbase + s * STAGE_B;
#pragma unroll
        for (int ks = 0; ks < 2; ks++) {
            const int kb = ks * 32;
            uint32_t ahi[4][4], alo[4][4];
#pragma unroll
            for (int mf = 0; mf < 4; mf++) {
                uint32_t ad = sb + (wm + mf * 16 + a_row) * ROWB + kb + a_cb;
                ldsm4(ahi[mf], ad);
                ldsm4(alo[mf], ad + TILE_B);
            }
            uint32_t bhi[4][2], blo[4][2];
#pragma unroll
            for (int nf = 0; nf < 4; nf++) {
                uint32_t bd = sb + 2 * TILE_B + (wn + nf * 8 + b_row) * ROWB + kb + b_cb;
                ldsm2(bhi[nf], bd);
                ldsm2(blo[nf], bd + TILE_B);
            }
#pragma unroll
            for (int mf = 0; mf < 4; mf++)
#pragma unroll
                for (int nf = 0; nf < 4; nf++) {
                    mma16816(acc[mf][nf], ahi[mf], bhi[nf]);
                    mma16816(acc[mf][nf], ahi[mf], blo[nf]);
                    mma16816(acc[mf][nf], alo[mf], bhi[nf]);
                }
        }
        __syncthreads();
        if (c + 1 < nch) {
            char* st = smc + (s ^ 1) * STAGE_B;
#pragma unroll
            for (int i = 0; i < 4; i++) {
                int f4 = lf4 + i;
                uint32_t h01, h23, l01, l23;
                cvt_hilo(ra[i].x, ra[i].y, h01, l01);
                cvt_hilo(ra[i].z, ra[i].w, h23, l23);
                int off = lrow * ROWB + f4 * 8;
                *(uint2*)(st + off)          = make_uint2(h01, h23);
                *(uint2*)(st + TILE_B + off) = make_uint2(l01, l23);
                cvt_hilo(rb[i].x, rb[i].y, h01, l01);
                cvt_hilo(rb[i].z, rb[i].w, h23, l23);
                *(uint2*)(st + 2 * TILE_B + off) = make_uint2(h01, h23);
                *(uint2*)(st + 3 * TILE_B + off) = make_uint2(l01, l23);
            }
            __syncthreads();
        }
    }

    // epilogue
#pragma unroll
    for (int mf = 0; mf < 4; mf++) {
        int rbase = m0 + wm + mf * 16 + (lane >> 2);
#pragma unroll
        for (int nf = 0; nf < 4; nf++) {
            int cb = n0 + wn + nf * 8 + (lane & 3) * 2;
#pragma unroll
            for (int hlf = 0; hlf < 2; hlf++) {
                int row = rbase + hlf * 8;
                float vx = acc[mf][nf][hlf * 2];
                float vy = acc[mf][nf][hlf * 2 + 1];
                if (Add) {
                    const float* ap = Add + (size_t)row * ldc + cb;
                    vx += ap[0]; vy += ap[1];
                }
                if (act == 1) { vx = gelu_tanh(vx); vy = gelu_tanh(vy); }
                float2* cp = (float2*)(C + (size_t)row * ldc + cb);
                *cp = make_float2(vx, vy);
            }
        }
    }
}

// Wrappers
__global__ void __launch_bounds__(256) k_hg_main(
    const float* __restrict__ A, const float* __restrict__ Bt,
    float* __restrict__ C, const float* __restrict__ Add,
    int Kd, int ldc, int act)
{
    hgemm_body(A, Kd, Bt, Kd, C, ldc, Add, Kd, act);
}

__global__ void __launch_bounds__(256) k_hg_scores() {
    if (blockIdx.x * 128 > blockIdx.y * 128 + 127) return;  // fully masked tile
    int z = blockIdx.z;
    int b = z >> 4, h = z & 15;
    const float* A  = g_qkv + (size_t)b * KK * QLD + (size_t)h * HD;       // Q
    const float* Bt = g_qkv + (size_t)b * KK * QLD + (size_t)h * HD + Dd;  // K
    float* C = g_scores + (size_t)z * KK * KK;
    hgemm_body(A, QLD, Bt, QLD, C, KK, nullptr, HD, 0);
}

__global__ void __launch_bounds__(256) k_hg_av() {
    int z = blockIdx.z;
    int b = z >> 4, h = z & 15;
    const float* A  = g_scores + (size_t)z * KK * KK;
    const float* Bt = g_vT + (size_t)z * HD * KK;
    float* C = g_att + (size_t)b * KK * Dd + (size_t)h * HD;
    int Keff = (blockIdx.y + 1) * 128;   // causal: probs are exactly 0 beyond
    hgemm_body(A, KK, Bt, KK, C, Dd, nullptr, Keff, 0);
}

// ----------------------------------------------------------------------------
// Transposes
// ----------------------------------------------------------------------------
__global__ void k_transpose(const float* __restrict__ W, float* __restrict__ WT,
                            int Kd, int Nd) {
    __shared__ float t[32][33];
    int k0 = blockIdx.y * 32, n0 = blockIdx.x * 32;
    int x = threadIdx.x, y = threadIdx.y;
#pragma unroll
    for (int i = 0; i < 32; i += 8)
        t[y + i][x] = W[(size_t)(k0 + y + i) * Nd + n0 + x];
    __syncthreads();
#pragma unroll
    for (int i = 0; i < 32; i += 8)
        WT[(size_t)(n0 + y + i) * Kd + k0 + x] = t[x][y + i];
}

__global__ void k_vt() {   // g_qkv V slice [b][tok][h][d] -> g_vT [b*H+h][d][tok]
    __shared__ float t[32][33];
    int z = blockIdx.z, b = z >> 4, h = z & 15;
    int tok0 = blockIdx.x * 32, d0 = blockIdx.y * 32;
    int x = threadIdx.x, y = threadIdx.y;
#pragma unroll
    for (int i = 0; i < 32; i += 8)
        t[y + i][x] = g_qkv[(size_t)(b * KK + tok0 + y + i) * QLD + 2 * Dd + h * HD + d0 + x];
    __syncthreads();
#pragma unroll
    for (int i = 0; i < 32; i += 8)
        g_vT[(size_t)z * HD * KK + (size_t)(d0 + y + i) * KK + tok0 + x] = t[x][y + i];
}

// ----------------------------------------------------------------------------
// Router / select / gather
// ----------------------------------------------------------------------------
__global__ void k_router(const float* __restrict__ hidden, const float* __restrict__ rw) {
    int wid  = (blockIdx.x * blockDim.x + threadIdx.x) >> 5;
    int lane = threadIdx.x & 31;
    if (wid >= Bb * Ss) return;
    const float4* x  = (const float4*)(hidden + (size_t)wid * Dd);
    const float4* r4 = (const float4*)rw;
    float s = 0.f;
#pragma unroll 4
    for (int i = lane; i < Dd / 4; i += 32) {
        float4 a = x[i], b = r4[i];
        s += a.x * b.x + a.y * b.y + a.z * b.z + a.w * b.w;
    }
    s = warpReduceSum(s);
    if (lane == 0) g_weights[wid] = 1.f / (1.f + expf(-s));
}

__global__ void k_select(const int* __restrict__ pos_ids) {
    __shared__ float w[Ss];
    __shared__ unsigned char sel[Ss];
    int b = blockIdx.x;
    for (int s = threadIdx.x; s < Ss; s += blockDim.x) w[s] = g_weights[b * Ss + s];
    __syncthreads();
    for (int s = threadIdx.x; s < Ss; s += blockDim.x) {
        float ws = w[s];
        int r = 0;
        for (int t = 0; t < Ss; t++) {
            float wt = w[t];
            r += (wt > ws) || (wt == ws && t < s);
        }
        sel[s] = (r < KK) ? 1 : 0;
    }
    __syncthreads();
    for (int s = threadIdx.x; s < Ss; s += blockDim.x) {
        if (sel[s]) {
            int j = 0;
            for (int t = 0; t < s; t++) j += sel[t];
            g_kidx[b * KK + j] = s;
            g_kpos[b * KK + j] = pos_ids[s];
            g_inv [b * Ss + s] = j;
        } else {
            g_inv [b * Ss + s] = -1;
        }
    }
}

// 256 threads/token; thread owns 8 consecutive columns -> vector accesses
__global__ void k_gather_rms1(const float* __restrict__ hidden, const float* __restrict__ ln1w) {
    int t = blockIdx.x;
    int b = t >> 10;
    int s = g_kidx[t];
    const float* src = hidden + ((size_t)(b * Ss + s)) * Dd;
    float* xdst = g_X  + (size_t)t * Dd;
    float* hdst = g_h1 + (size_t)t * Dd;
    int c0 = threadIdx.x * 8;
    float loc[8];
    *(float4*)&loc[0] = *(const float4*)&src[c0];
    *(float4*)&loc[4] = *(const float4*)&src[c0 + 4];
    float ss = 0.f;
#pragma unroll
    for (int i = 0; i < 8; i++) ss += loc[i] * loc[i];
    ss = blockReduceSum(ss);
    float r = rsqrtf(ss * (1.f / Dd) + EPSf);
    *(float4*)&xdst[c0]     = *(float4*)&loc[0];
    *(float4*)&xdst[c0 + 4] = *(float4*)&loc[4];
    float o[8];
#pragma unroll
    for (int i = 0; i < 8; i++) o[i] = loc[i] * r * ln1w[c0 + i];
    *(float4*)&hdst[c0]     = *(float4*)&o[0];
    *(float4*)&hdst[c0 + 4] = *(float4*)&o[4];
}

// ----------------------------------------------------------------------------
// RoPE on fused qkv buffer (fp32 in-place, float2 vectorized)
// ----------------------------------------------------------------------------
__global__ void k_rope() {
    int t = blockIdx.x * blockDim.x + threadIdx.x;   // MTOT * H * 32
    if (t >= MTOT * Hh * 32) return;
    int dp  = (t & 31) * 2;
    int th  = t >> 5;
    int h   = th & 15;
    int tok = th >> 4;
    int pos = g_kpos[tok];
    float fp = (float)pos;
    float f0 = expf((float)dp       * (-9.210340371976184f / 64.f));
    float f1 = expf((float)(dp + 1) * (-9.210340371976184f / 64.f));
    float c0 = cosf(fp * f0), s0 = sinf(fp * f0);
    float c1 = cosf(fp * f1), s1 = sinf(fp * f1);
    size_t qb = (size_t)tok * QLD + h * HD + dp;     // Q slice
    size_t kb = qb + Dd;                              // K slice
    float2 q1 = *(float2*)&g_qkv[qb];
    float2 q2 = *(float2*)&g_qkv[qb + HALF];
    *(float2*)&g_qkv[qb]        = make_float2(q1.x * c0 - q2.x * s0, q1.y * c1 - q2.y * s1);
    *(float2*)&g_qkv[qb + HALF] = make_float2(q2.x * c0 + q1.x * s0, q2.y * c1 + q1.y * s1);
    float2 k1 = *(float2*)&g_qkv[kb];
    float2 k2 = *(float2*)&g_qkv[kb + HALF];
    *(float2*)&g_qkv[kb]        = make_float2(k1.x * c0 - k2.x * s0, k1.y * c1 - k2.y * s1);
    *(float2*)&g_qkv[kb + HALF] = make_float2(k2.x * c0 + k1.x * s0, k2.y * c1 + k1.y * s1);
}

// ----------------------------------------------------------------------------
// Softmax: 128 threads/row, thread owns 8 cols; only covering tiles touched
// ----------------------------------------------------------------------------
__global__ void k_softmax() {
    int row = blockIdx.x;
    int q = row & (KK - 1);
    float* r = g_scores + (size_t)row * KK;
    int n = q + 1;
    int ncov = ((q >> 7) + 1) << 7;          // AV reads exactly [0, ncov)
    int c0 = threadIdx.x * 8;
    bool active = (c0 < ncov);
    float v[8];
    if (active) {
        *(float4*)&v[0] = *(const float4*)&r[c0];
        *(float4*)&v[4] = *(const float4*)&r[c0 + 4];
    }
    float m = -FLT_MAX;
    if (active) {
#pragma unroll
        for (int i = 0; i < 8; i++)
            if (c0 + i < n) m = fmaxf(m, v[i]);
    }
    m = blockReduceMax(m);
    float e[8];
    float sum = 0.f;
    if (active) {
#pragma unroll
        for (int i = 0; i < 8; i++) {
            e[i] = (c0 + i < n) ? expf(SM_SCALE * (v[i] - m)) : 0.f;
            sum += e[i];
        }
    }
    sum = blockReduceSum(sum);
    if (active) {
        float inv = 1.f / sum;
#pragma unroll
        for (int i = 0; i < 8; i++) e[i] *= inv;
        *(float4*)&r[c0]     = *(float4*)&e[0];
        *(float4*)&r[c0 + 4] = *(float4*)&e[4];
    }
}

// ----------------------------------------------------------------------------
// h2 = X + ao ; rmsnorm -> fp32 (vectorized)
// ----------------------------------------------------------------------------
__global__ void k_h2rms(const float* __restrict__ ln2w) {
    int t = blockIdx.x;
    const float* xa = g_X  + (size_t)t * Dd;
    const float* ao = g_ao + (size_t)t * Dd;
    float* dst = g_h2n + (size_t)t * Dd;
    int c0 = threadIdx.x * 8;
    float loc[8];
#pragma unroll
    for (int i = 0; i < 8; i += 4) {
        float4 a = *(const float4*)&xa[c0 + i];
        float4 b = *(const float4*)&ao[c0 + i];
        loc[i] = a.x + b.x; loc[i + 1] = a.y + b.y;
        loc[i + 2] = a.z + b.z; loc[i + 3] = a.w + b.w;
    }
    float ss = 0.f;
#pragma unroll
    for (int i = 0; i < 8; i++) ss += loc[i] * loc[i];
    ss = blockReduceSum(ss);
    float r = rsqrtf(ss * (1.f / Dd) + EPSf);
    float o[8];
#pragma unroll
    for (int i = 0; i < 8; i++) o[i] = loc[i] * r * ln2w[c0 + i];
    *(float4*)&dst[c0]     = *(float4*)&o[0];
    *(float4*)&dst[c0 + 4] = *(float4*)&o[4];
}

// ----------------------------------------------------------------------------
// Final output: kept rows = delta*w + kept ; others = hidden*w (single pass)
// ----------------------------------------------------------------------------
__global__ void k_final(const float* __restrict__ hidden, float* __restrict__ out) {
    int row = blockIdx.x;                 // 0 .. Bb*Ss-1
    int b   = row >> 11;                  // / Ss
    int inv = g_inv[row];
    float w = g_weights[row];
    float* o = out + (size_t)row * Dd;
    int c0 = threadIdx.x * 8;
    if (inv >= 0) {
        size_t t = ((size_t)(b * KK + inv)) * Dd;
        const float* dl = g_delta + t;
        const float* xk = g_X + t;
#pragma unroll
        for (int i = 0; i < 8; i += 4) {
            float4 d4 = *(const float4*)&dl[c0 + i];
            float4 x4 = *(const float4*)&xk[c0 + i];
            *(float4*)&o[c0 + i] = make_float4(d4.x * w + x4.x, d4.y * w + x4.y,
                                               d4.z * w + x4.z, d4.w * w + x4.w);
        }
    } else {
        const float* h = hidden + (size_t)row * Dd;
#pragma unroll
        for (int i = 0; i < 8; i += 4) {
            float4 h4 = *(const float4*)&h[c0 + i];
            *(float4*)&o[c0 + i] = make_float4(h4.x * w, h4.y * w, h4.z * w, h4.w * w);
        }
    }
}

// ----------------------------------------------------------------------------
// Launch (graph-capturable fork-join via events: parallel branches in the graph)
// ----------------------------------------------------------------------------
extern "C" void kernel_launch(void* const* d_in, const int* in_sizes, int n_in,
                              void* d_out, int out_size) {
    const float* hidden   = (const float*)d_in[0];
    const int*   pos_ids  = (const int*)d_in[1];
    const float* router_w = (const float*)d_in[4];
    const float* ln1w     = (const float*)d_in[5];
    const float* ln2w     = (const float*)d_in[6];
    const float* Wq       = (const float*)d_in[7];
    const float* Wk       = (const float*)d_in[8];
    const float* Wv       = (const float*)d_in[9];
    const float* Wo       = (const float*)d_in[10];
    const float* W1       = (const float*)d_in[11];
    const float* W2       = (const float*)d_in[12];
    float* out = (float*)d_out;

    cudaFuncSetAttribute(k_hg_main,   cudaFuncAttributeMaxDynamicSharedMemorySize, HG_SMEM);
    cudaFuncSetAttribute(k_hg_scores, cudaFuncAttributeMaxDynamicSharedMemorySize, HG_SMEM);
    cudaFuncSetAttribute(k_hg_av,     cudaFuncAttributeMaxDynamicSharedMemorySize, HG_SMEM);

#define SYM(p, g) cudaGetSymbolAddress((void**)&p, g)
    float *WqkvT, *WoT, *W1T, *W2T;
    float *h1, *qkv, *att, *ao, *h2n, *ffh, *dlt;
    SYM(WqkvT, g_WqkvT); SYM(WoT, g_WoT);
    SYM(W1T, g_W1T); SYM(W2T, g_W2T);
    SYM(h1, g_h1); SYM(qkv, g_qkv);
    SYM(att, g_att); SYM(ao, g_ao); SYM(h2n, g_h2n);
    SYM(ffh, g_ffh); SYM(dlt, g_delta);
#undef SYM

    // side stream + events for fork-join (not destroyed: destroying a stream
    // that participated in an active capture invalidates the capture; handles
    // are host-side and few calls occur).
    cudaStream_t s1;
    cudaStreamCreateWithFlags(&s1, cudaStreamNonBlocking);
    cudaEvent_t eF1, eJ1, eF2, eJ2;
    cudaEventCreateWithFlags(&eF1, cudaEventDisableTiming);
    cudaEventCreateWithFlags(&eJ1, cudaEventDisableTiming);
    cudaEventCreateWithFlags(&eF2, cudaEventDisableTiming);
    cudaEventCreateWithFlags(&eJ2, cudaEventDisableTiming);

    dim3 tb(32, 8);
    const size_t DD = (size_t)Dd * Dd;

    // ---- fork 1: weight transposes (s1)  ∥  router->select->gather (s0) ----
    cudaEventRecord(eF1, 0);
    cudaStreamWaitEvent(s1, eF1, 0);

    k_transpose<<<dim3(Dd / 32, Dd / 32), tb, 0, s1>>>(Wq, WqkvT,          Dd, Dd);
    k_transpose<<<dim3(Dd / 32, Dd / 32), tb, 0, s1>>>(Wk, WqkvT + DD,     Dd, Dd);
    k_transpose<<<dim3(Dd / 32, Dd / 32), tb, 0, s1>>>(Wv, WqkvT + 2 * DD, Dd, Dd);
    k_transpose<<<dim3(Dd / 32, Dd / 32), tb, 0, s1>>>(Wo, WoT, Dd, Dd);
    k_transpose<<<dim3(FFd / 32, Dd / 32), tb, 0, s1>>>(W1, W1T, Dd, FFd);
    k_transpose<<<dim3(Dd / 32, FFd / 32), tb, 0, s1>>>(W2, W2T, FFd, Dd);

    k_router<<<(Bb * Ss) / 8, 256>>>(hidden, router_w);
    k_select<<<Bb, 1024>>>(pos_ids);
    k_gather_rms1<<<MTOT, 256>>>(hidden, ln1w);

    cudaEventRecord(eJ1, s1);
    cudaStreamWaitEvent(0, eJ1, 0);

    // fused QKV: C is [MTOT][3*Dd], B rows 0..6143 = Wq|Wk|Wv transposed
    k_hg_main<<<dim3(QLD / 128, MTOT / 128), 256, HG_SMEM>>>(
        h1, WqkvT, qkv, nullptr, Dd, QLD, 0);

    // ---- fork 2: vt (s1)  ∥  rope->scores->softmax (s0); join before AV ----
    cudaEventRecord(eF2, 0);
    cudaStreamWaitEvent(s1, eF2, 0);

    k_vt<<<dim3(KK / 32, HD / 32, BH), tb, 0, s1>>>();

    k_rope<<<(MTOT * Hh * 32 + 255) / 256, 256>>>();
    k_hg_scores<<<dim3(KK / 128, KK / 128, BH), 256, HG_SMEM>>>();
    k_softmax<<<BH * KK, 128>>>();

    cudaEventRecord(eJ2, s1);
    cudaStreamWaitEvent(0, eJ2, 0);

    k_hg_av<<<dim3(1, KK / 128, BH), 256, HG_SMEM>>>();

    dim3 gD(Dd / 128, MTOT / 128);
    k_hg_main<<<gD, 256, HG_SMEM>>>(att, WoT, ao, nullptr, Dd, Dd, 0);
    k_h2rms<<<MTOT, 256>>>(ln2w);
    k_hg_main<<<dim3(FFd / 128, MTOT / 128), 256, HG_SMEM>>>(h2n, W1T, ffh, nullptr, Dd, FFd, 1);
    k_hg_main<<<gD, 256, HG_SMEM>>>(ffh, W2T, dlt, ao, FFd, Dd, 0);

    k_final<<<Bb * Ss, 256>>>(hidden, out);
}